// round 12
// baseline (speedup 1.0000x reference)
#include <cuda_runtime.h>
#include <math.h>

typedef unsigned int u32;

#define BB 8
#define TT 256
#define EE 512
#define FF 2048
#define DD 256
#define NN 2048
#define LL 2
#define VV 32000
#define HMM 4
#define HDD 64
#define HAA 8
#define DHH 64
#define IFF 1028
#define TOPKK 8
#define MAXSEL 64

// weight-plane arena offsets (u32 units). Per-weight contiguous across layers.
#define OFF_QKVO_W(w) ((w)*262144)             // + l*131072
#define OFF_W1  1048576                        // + l*524288
#define OFF_W2  2097152                        // + l*524288
#define OFF_WIFH 3145728
#define OFF_WLG  3408896
#define ARENA    15696896

// ---- scratch ----
__device__ float g_x[BB*TT*EE];
__device__ float g_q[BB*TT*EE];
__device__ float g_k[BB*TT*EE];
__device__ float g_v[BB*TT*EE];
__device__ float g_s[BB*HAA*TT*TT];
__device__ float g_iface[BB*TT*IFF];
__device__ float g_mem[BB*NN*HMM*HDD];
__device__ float g_norminv[BB*NN*HMM];
__device__ float g_rvbuf[2][BB*DD];
__device__ u32   g_bar[BB];
__device__ u32   g_wh[ARENA];
__device__ u32   g_wl[ARENA];
__device__ u32   g_ah[2048*1024];   // u planes (lda2=1024) / vocab-A planes (lda2=384)
__device__ u32   g_al[2048*1024];
__device__ u32   g_bh[2048*256];    // ln / attn_o planes (lda2=256)
__device__ u32   g_bl[2048*256];

__device__ __forceinline__ float gelu_f(float x){
    float x3 = x*x*x;
    return 0.5f*x*(1.0f+tanhf(0.7978845608028654f*(x+0.044715f*x3)));
}
__device__ __forceinline__ float sigmoid_f(float x){ return 1.0f/(1.0f+expf(-x)); }
__device__ __forceinline__ float softplus_clip(float x){
    float sp = fmaxf(x,0.0f) + log1pf(expf(-fabsf(x)));
    return fminf(fmaxf(sp,1.0f),20.0f);
}

__device__ __forceinline__ void packpair(float e, float o, u32 &hi, u32 &lo){
    u32 h; asm("cvt.rn.bf16x2.f32 %0, %1, %2;" : "=r"(h) : "f"(o), "f"(e));
    float he = __uint_as_float(h<<16);
    float ho = __uint_as_float(h & 0xffff0000u);
    asm("cvt.rn.bf16x2.f32 %0, %1, %2;" : "=r"(lo) : "f"(o-ho), "f"(e-he));
    hi = h;
}

__device__ __forceinline__ void mma_bf16(float* c, const u32* a, const u32* b){
    asm volatile("mma.sync.aligned.m16n8k16.row.col.f32.bf16.bf16.f32 "
        "{%0,%1,%2,%3}, {%4,%5,%6,%7}, {%8,%9}, {%0,%1,%2,%3};\n"
        : "+f"(c[0]), "+f"(c[1]), "+f"(c[2]), "+f"(c[3])
        : "r"(a[0]), "r"(a[1]), "r"(a[2]), "r"(a[3]), "r"(b[0]), "r"(b[1]));
}

__device__ __forceinline__ u32 s2u(const void* p){ return (u32)__cvta_generic_to_shared(p); }
__device__ __forceinline__ void cp16(u32 d, const void* s){
    asm volatile("cp.async.cg.shared.global [%0], [%1], 16;\n"::"r"(d),"l"(s));
}
__device__ __forceinline__ void cp16z(u32 d, const void* s, int sz){
    asm volatile("cp.async.cg.shared.global [%0], [%1], 16, %2;\n"::"r"(d),"l"(s),"r"(sz));
}
__device__ __forceinline__ void cp_commit(){ asm volatile("cp.async.commit_group;\n"); }
__device__ __forceinline__ void cp_wait0(){ asm volatile("cp.async.wait_group 0;\n"); }

__device__ __forceinline__ void red_release(u32* p, u32 v){
    asm volatile("red.release.gpu.global.add.u32 [%0], %1;" :: "l"(p), "r"(v) : "memory");
}
__device__ __forceinline__ u32 ld_acquire(const u32* p){
    u32 v; asm volatile("ld.acquire.gpu.global.u32 %0, [%1];" : "=r"(v) : "l"(p) : "memory");
    return v;
}

// ---- weight split: f32 [K][N] -> hi/lo u32 planes [K/2][N] ----
__global__ void wsplit_kernel(const float* __restrict__ src, u32* __restrict__ dh,
                              u32* __restrict__ dl, int N){
    int k2 = blockIdx.y;
    int n = blockIdx.x*256 + threadIdx.x;
    if (n >= N) return;
    float e = src[(size_t)(2*k2)*N + n];
    float o = src[(size_t)(2*k2+1)*N + n];
    u32 hi, lo; packpair(e, o, hi, lo);
    dh[(size_t)k2*N + n] = hi;
    dl[(size_t)k2*N + n] = lo;
}

// ---- embedding ----
__global__ void embed_kernel(const int* __restrict__ ids,
                             const float* __restrict__ emb,
                             const float* __restrict__ pos){
    int bt = blockIdx.x;
    int t = bt & (TT-1);
    int id = ids[bt];
    for (int e = threadIdx.x; e < EE; e += 256)
        g_x[(size_t)bt*EE + e] = emb[(size_t)id*EE + e] + pos[(size_t)t*EE + e];
}

// ---- layernorm with split (plane) output ----
__global__ void ln_split_kernel(const float* __restrict__ x, const float* __restrict__ g,
                                const float* __restrict__ bb, u32* __restrict__ oh,
                                u32* __restrict__ ol, int lda2){
    int row = blockIdx.x, tid = threadIdx.x;
    __shared__ float red[256];
    const float* xr = x + (size_t)row*EE;
    float v0 = xr[2*tid], v1 = xr[2*tid+1];
    red[tid] = v0+v1; __syncthreads();
    for (int s=128;s>0;s>>=1){ if (tid<s) red[tid]+=red[tid+s]; __syncthreads(); }
    float m = red[0] * (1.0f/EE);
    __syncthreads();
    float d0=v0-m, d1=v1-m;
    red[tid] = d0*d0 + d1*d1; __syncthreads();
    for (int s=128;s>0;s>>=1){ if (tid<s) red[tid]+=red[tid+s]; __syncthreads(); }
    float rs = rsqrtf(red[0]*(1.0f/EE) + 1e-5f);
    float y0 = d0*rs*g[2*tid]   + bb[2*tid];
    float y1 = d1*rs*g[2*tid+1] + bb[2*tid+1];
    u32 hi, lo; packpair(y0, y1, hi, lo);
    oh[(size_t)row*lda2 + tid] = hi;
    ol[(size_t)row*lda2 + tid] = lo;
}

// ---- bf16x3 tensor GEMM, cp.async double-buffered; optional split-plane output ----
template<bool ACC, bool GELU, bool BIAS, bool NGUARD, bool OSPLIT>
__global__ __launch_bounds__(256)
void bgemm_kernel(const u32* __restrict__ AH, const u32* __restrict__ AL, int lda2,
                  const u32* __restrict__ BH, const u32* __restrict__ BL,
                  const float* __restrict__ bias, float* __restrict__ C,
                  u32* __restrict__ OH, u32* __restrict__ OL, int lda2o,
                  int N, int K2)
{
    __shared__ u32 AsH[2][128*12], AsL[2][128*12];
    __shared__ u32 BsH[2][8][136], BsL[2][8][136];
    int tid = threadIdx.x;
    int bm = blockIdx.y*128, bn = blockIdx.x*128;
    int warp = tid>>5, lane = tid&31;
    int wm = (warp>>2)*64, wn = (warp&3)*32;
    int gid = lane>>2, tig = lane&3;

    float c[4][4][4];
    #pragma unroll
    for (int mt=0;mt<4;mt++)
        #pragma unroll
        for (int nt=0;nt<4;nt++)
            #pragma unroll
            for (int i=0;i<4;i++) c[mt][nt][i]=0.f;

    int am = tid & 127, akp = (tid>>7)*4;
    int bk = tid>>5, bn4 = lane*4;
    const u32* AHp = AH + (size_t)(bm+am)*lda2 + akp;
    const u32* ALp = AL + (size_t)(bm+am)*lda2 + akp;
    int nit = K2/8;

    auto issueTile = [&](int buf, int it){
        cp16(s2u(&AsH[buf][am*12+akp]), AHp + (size_t)it*8);
        cp16(s2u(&AsL[buf][am*12+akp]), ALp + (size_t)it*8);
        int kr = it*8 + bk;
        const u32* ph_ = BH + (size_t)kr*N + bn + bn4;
        const u32* pl_ = BL + (size_t)kr*N + bn + bn4;
        if (!NGUARD){
            cp16(s2u(&BsH[buf][bk][bn4]), ph_);
            cp16(s2u(&BsL[buf][bk][bn4]), pl_);
        } else {
            int col = bn + bn4;
            int sz = (N - col)*4; sz = sz<0?0:(sz>16?16:sz);
            cp16z(s2u(&BsH[buf][bk][bn4]), ph_, sz);
            cp16z(s2u(&BsL[buf][bk][bn4]), pl_, sz);
        }
    };

    issueTile(0, 0); cp_commit();

    int cur = 0;
    for (int it=0; it<nit; ++it){
        cp_wait0();
        __syncthreads();
        if (it+1 < nit){ issueTile(cur^1, it+1); cp_commit(); }

        u32 aH[4][4], aL[4][4];
        #pragma unroll
        for (int mt=0;mt<4;mt++){
            int m0 = wm + mt*16 + gid;
            aH[mt][0]=AsH[cur][m0*12     + tig  ]; aL[mt][0]=AsL[cur][m0*12     + tig  ];
            aH[mt][1]=AsH[cur][(m0+8)*12 + tig  ]; aL[mt][1]=AsL[cur][(m0+8)*12 + tig  ];
            aH[mt][2]=AsH[cur][m0*12     + tig+4]; aL[mt][2]=AsL[cur][m0*12     + tig+4];
            aH[mt][3]=AsH[cur][(m0+8)*12 + tig+4]; aL[mt][3]=AsL[cur][(m0+8)*12 + tig+4];
        }
        u32 bH[4][2], bL[4][2];
        #pragma unroll
        for (int nt=0;nt<4;nt++){
            int n0 = wn + nt*8 + gid;
            bH[nt][0]=BsH[cur][tig  ][n0]; bL[nt][0]=BsL[cur][tig  ][n0];
            bH[nt][1]=BsH[cur][tig+4][n0]; bL[nt][1]=BsL[cur][tig+4][n0];
        }
        #pragma unroll
        for (int mt=0;mt<4;mt++){
            #pragma unroll
            for (int nt=0;nt<4;nt++){
                mma_bf16(c[mt][nt], aH[mt], bH[nt]);
                mma_bf16(c[mt][nt], aH[mt], bL[nt]);
                mma_bf16(c[mt][nt], aL[mt], bH[nt]);
            }
        }
        cur ^= 1;
    }

    #pragma unroll
    for (int mt=0;mt<4;mt++){
        int ra = bm + wm + mt*16 + gid;
        int rb = ra + 8;
        #pragma unroll
        for (int nt=0;nt<4;nt++){
            int col = bn + wn + nt*8 + tig*2;
            if (OSPLIT){
                float v0 = c[mt][nt][0], v1 = c[mt][nt][1];
                float v2 = c[mt][nt][2], v3 = c[mt][nt][3];
                if (BIAS){ float b0=bias[col], b1=bias[col+1]; v0+=b0; v1+=b1; v2+=b0; v3+=b1; }
                if (GELU){ v0=gelu_f(v0); v1=gelu_f(v1); v2=gelu_f(v2); v3=gelu_f(v3); }
                u32 hi, lo;
                packpair(v0, v1, hi, lo);
                OH[(size_t)ra*lda2o + (col>>1)] = hi; OL[(size_t)ra*lda2o + (col>>1)] = lo;
                packpair(v2, v3, hi, lo);
                OH[(size_t)rb*lda2o + (col>>1)] = hi; OL[(size_t)rb*lda2o + (col>>1)] = lo;
            } else {
                #pragma unroll
                for (int q=0;q<4;q++){
                    int r = (q<2)? ra : rb;
                    int cc = col + (q&1);
                    if (NGUARD && cc >= N) continue;
                    float v = c[mt][nt][q];
                    if (BIAS) v += bias[cc];
                    if (GELU) v = gelu_f(v);
                    size_t idx = (size_t)r*N + cc;
                    if (ACC) v += C[idx];
                    C[idx] = v;
                }
            }
        }
    }
}

// ---- attention ----
__global__ void attn_s_kernel(){
    int bh = blockIdx.y;
    int b = bh >> 3, h = bh & 7;
    int qt = blockIdx.x >> 3, kt = blockIdx.x & 7;
    __shared__ float Qs[32][65];
    __shared__ float Ks[32][65];
    int tid = threadIdx.x;
    {
        int r = tid >> 3, cc = (tid & 7)*8;
        const float* qsrc = g_q + ((size_t)(b*TT + qt*32 + r))*EE + h*DHH + cc;
        const float* ksrc = g_k + ((size_t)(b*TT + kt*32 + r))*EE + h*DHH + cc;
        float4 q0 = *(const float4*)qsrc, q1 = *(const float4*)(qsrc+4);
        float4 k0 = *(const float4*)ksrc, k1 = *(const float4*)(ksrc+4);
        Qs[r][cc+0]=q0.x; Qs[r][cc+1]=q0.y; Qs[r][cc+2]=q0.z; Qs[r][cc+3]=q0.w;
        Qs[r][cc+4]=q1.x; Qs[r][cc+5]=q1.y; Qs[r][cc+6]=q1.z; Qs[r][cc+7]=q1.w;
        Ks[r][cc+0]=k0.x; Ks[r][cc+1]=k0.y; Ks[r][cc+2]=k0.z; Ks[r][cc+3]=k0.w;
        Ks[r][cc+4]=k1.x; Ks[r][cc+5]=k1.y; Ks[r][cc+6]=k1.z; Ks[r][cc+7]=k1.w;
    }
    __syncthreads();
    int r = tid & 31, gq = tid >> 5;
    float a0=0,a1=0,a2=0,a3=0;
    #pragma unroll
    for (int kk=0;kk<64;kk++){
        float qv = Qs[r][kk];
        a0 += qv*Ks[gq*4+0][kk];
        a1 += qv*Ks[gq*4+1][kk];
        a2 += qv*Ks[gq*4+2][kk];
        a3 += qv*Ks[gq*4+3][kk];
    }
    int qrow = qt*32 + r;
    int kc = kt*32 + gq*4;
    float* srow = g_s + ((size_t)bh*TT + qrow)*TT + kc;
    srow[0] = (kc+0<=qrow)? a0*0.125f : -1e30f;
    srow[1] = (kc+1<=qrow)? a1*0.125f : -1e30f;
    srow[2] = (kc+2<=qrow)? a2*0.125f : -1e30f;
    srow[3] = (kc+3<=qrow)? a3*0.125f : -1e30f;
}

__global__ void softmax_kernel(){
    int row = blockIdx.x, tid = threadIdx.x;
    __shared__ float red[256];
    float* sp = g_s + (size_t)row*TT;
    float v = sp[tid];
    red[tid]=v; __syncthreads();
    for (int s=128;s>0;s>>=1){ if (tid<s) red[tid]=fmaxf(red[tid],red[tid+s]); __syncthreads(); }
    float m = red[0]; __syncthreads();
    float e = expf(v-m);
    red[tid]=e; __syncthreads();
    for (int s=128;s>0;s>>=1){ if (tid<s) red[tid]+=red[tid+s]; __syncthreads(); }
    sp[tid] = e / red[0];
}

// O = A @ V, packed directly into bf16 hi/lo planes (g_bh/g_bl, lda2=256)
__global__ void attn_o_kernel(){
    int bh = blockIdx.y;
    int b = bh >> 3, h = bh & 7;
    int qt = blockIdx.x;
    __shared__ float As[32][65];
    __shared__ float Vs[64][64];
    int tid = threadIdx.x;
    int d = tid & 63, qg = tid >> 6;
    float acc[8];
    #pragma unroll
    for (int i=0;i<8;i++) acc[i]=0.f;
    for (int k0=0;k0<TT;k0+=64){
        {
            int r = tid >> 3, cc = (tid & 7)*8;
            const float* src = g_s + ((size_t)bh*TT + qt*32 + r)*TT + k0 + cc;
            float4 a0=*(const float4*)src, a1=*(const float4*)(src+4);
            As[r][cc+0]=a0.x; As[r][cc+1]=a0.y; As[r][cc+2]=a0.z; As[r][cc+3]=a0.w;
            As[r][cc+4]=a1.x; As[r][cc+5]=a1.y; As[r][cc+6]=a1.z; As[r][cc+7]=a1.w;
        }
        #pragma unroll
        for (int i=0;i<4;i++){
            int fl = (tid + 256*i)*4;
            int r = fl >> 6, cc = fl & 63;
            float4 vv = *(const float4*)(g_v + ((size_t)(b*TT + k0 + r))*EE + h*DHH + cc);
            *(float4*)&Vs[r][cc] = vv;
        }
        __syncthreads();
        #pragma unroll
        for (int kk=0;kk<64;kk++){
            float vv = Vs[kk][d];
            #pragma unroll
            for (int i=0;i<8;i++) acc[i] += As[qg*8+i][kk]*vv;
        }
        __syncthreads();
    }
    #pragma unroll
    for (int i=0;i<8;i++){
        int qr = qt*32 + qg*8 + i;
        float other = __shfl_xor_sync(0xffffffffu, acc[i], 1);
        if ((d & 1) == 0){
            u32 hi, lo; packpair(acc[i], other, hi, lo);
            int pc = (h*DHH + d) >> 1;
            size_t row = (size_t)(b*TT + qr);
            g_bh[row*256 + pc] = hi;
            g_bl[row*256 + pc] = lo;
        }
    }
}

// ---- init ----
__global__ void meminit_kernel(const float* __restrict__ mi){
    int idx = blockIdx.x*256 + threadIdx.x;
    g_mem[idx] = mi[idx & (NN*DD - 1)];
}
__global__ void norminit_kernel(){
    int gw = blockIdx.x*8 + (threadIdx.x>>5);
    int lane = threadIdx.x & 31;
    const float2* mrow = (const float2*)(g_mem + (size_t)gw*HDD);
    float2 v = mrow[lane];
    float ss = v.x*v.x + v.y*v.y;
    #pragma unroll
    for (int o=16;o>0;o>>=1) ss += __shfl_xor_sync(0xffffffffu, ss, o);
    if (lane==0) g_norminv[gw] = rsqrtf(ss + 1e-8f);
}
__global__ void scaninit_kernel(){
    int i = blockIdx.x*256 + threadIdx.x;
    g_rvbuf[0][i] = 0.f;
    if (i < BB) g_bar[i] = 0u;
}

// ---- persistent fused scan, 1024 threads per (b,h) block ----
__global__ __launch_bounds__(1024,1)
void scan_persist_kernel(const float* __restrict__ Wr,
                         const float* __restrict__ pbr,
                         const float* __restrict__ pbw)
{
    int bh = blockIdx.x;
    int b = bh >> 2, h = bh & 3;
    int tid = threadIdx.x, warp = tid>>5, lane = tid&31;

    __shared__ float rv_s[DD];
    __shared__ float ifc_s[256];
    __shared__ float pmat[16][256];
    __shared__ __align__(16) float knr[HDD];
    __shared__ __align__(16) float knw[HDD];
    __shared__ float simr[NN], simw[NN];
    __shared__ float gr_sh;
    __shared__ float candv[2][128];
    __shared__ float s_kth[2], s_smax[2];
    __shared__ int   s_cnt[2];
    __shared__ int   sel_idx[2][MAXSEL];
    __shared__ float sel_w[2][MAXSEL];
    __shared__ float s_inv[2];

    float beta_r = softplus_clip(*pbr);
    float beta_w = softplus_clip(*pbw);

    for (int t=0; t<TT; ++t){
        if (tid < DD) rv_s[tid] = __ldcg(&g_rvbuf[t&1][b*DD + tid]);
        if (tid==0){ s_cnt[0]=0; s_cnt[1]=0; }
        __syncthreads();
        // record rv carry directly as bf16 split planes (cols 256..383 of vocab A)
        if (h == 0 && tid < 128){
            u32 hi, lo; packpair(rv_s[2*tid], rv_s[2*tid+1], hi, lo);
            size_t row = (size_t)(b*TT + t);
            g_ah[row*384 + 256 + tid] = hi;
            g_al[row*384 + 256 + tid] = lo;
        }

        // iface matvec: 64 col-quads x 16 d-groups (16 float4 iters per thread)
        {
            int cq = tid & 63, dg = tid >> 6;       // dg 0..15
            int seg = cq >> 4, cl4 = (cq & 15)*4;
            int col = seg*DD + h*HDD + cl4;
            const float* wp = Wr + (size_t)(dg*16)*IFF + col;
            float ax=0.f, ay=0.f, az=0.f, aw=0.f;
            #pragma unroll
            for (int d=0; d<16; ++d){
                float r = rv_s[dg*16 + d];
                float4 w = *reinterpret_cast<const float4*>(wp + (size_t)d*IFF);
                ax += r*w.x; ay += r*w.y; az += r*w.z; aw += r*w.w;
            }
            int p = seg*64 + cl4;
            pmat[dg][p+0]=ax; pmat[dg][p+1]=ay; pmat[dg][p+2]=az; pmat[dg][p+3]=aw;
        }
        if (tid < 32){
            int col = 4*DD + h;
            float acc = 0.f;
            for (int d=tid; d<DD; d+=32) acc += rv_s[d]*Wr[(size_t)d*IFF + col];
            #pragma unroll
            for (int o=16;o>0;o>>=1) acc += __shfl_xor_sync(0xffffffffu, acc, o);
            if (tid==0) gr_sh = acc + g_iface[(size_t)(b*TT + t)*IFF + col];
        }
        __syncthreads();
        if (tid < 256){
            int grp = tid >> 6, l = tid & 63;
            int col = grp*DD + h*HDD + l;
            float s = g_iface[(size_t)(b*TT + t)*IFF + col];
            #pragma unroll
            for (int dg=0; dg<16; ++dg) s += pmat[dg][tid];
            ifc_s[tid] = s;
        }
        __syncthreads();

        // normalize keys
        if (tid < 64){
            int w = tid >> 5, l = tid & 31;
            float v0 = ifc_s[w*64 + l], v1 = ifc_s[w*64 + l + 32];
            float ss = v0*v0 + v1*v1;
            #pragma unroll
            for (int o=16;o>0;o>>=1) ss += __shfl_xor_sync(0xffffffffu, ss, o);
            float rn = rsqrtf(ss + 1e-8f);
            float* dst = w ? knw : knr;
            dst[l] = v0*rn; dst[l+32] = v1*rn;
        }
        __syncthreads();

        // sims: 2 rows per thread, cached inverse norms, zero shuffles
        #pragma unroll
        for (int j=0;j<2;j++){
            int n = j*1024 + tid;
            const float4* mrow = (const float4*)(g_mem + (((size_t)b*NN + n)*HMM + h)*HDD);
            float dr=0.f, dw=0.f;
            #pragma unroll
            for (int c2=0;c2<16;c2++){
                float4 m  = mrow[c2];
                float4 kr = *(const float4*)&knr[c2*4];
                float4 kw = *(const float4*)&knw[c2*4];
                dr += m.x*kr.x + m.y*kr.y + m.z*kr.z + m.w*kr.w;
                dw += m.x*kw.x + m.y*kw.y + m.z*kw.z + m.w*kw.w;
            }
            float ninv = g_norminv[((size_t)b*NN + n)*HMM + h];
            simr[n] = dr*ninv;
            simw[n] = dw*ninv;
        }
        __syncthreads();

        // warp-parallel topk stage 1: 16 warps per phase, 128 sims per warp
        {
            int ph = warp >> 4, wi = warp & 15;
            const float* sim = ph ? simw : simr;
            float lv[4];
            #pragma unroll
            for (int j=0;j<4;j++) lv[j] = sim[wi*128 + j*32 + lane];
            #pragma unroll
            for (int it=0; it<TOPKK; ++it){
                float m=-3.4e38f; int mi=0;
                #pragma unroll
                for (int j=0;j<4;j++) if (lv[j]>m){ m=lv[j]; mi=j; }
                float bm=m; int bl=lane;
                #pragma unroll
                for (int o=16;o>0;o>>=1){
                    float om=__shfl_xor_sync(0xffffffffu,bm,o);
                    int   ol=__shfl_xor_sync(0xffffffffu,bl,o);
                    if (om>bm || (om==bm && ol<bl)){ bm=om; bl=ol; }
                }
                if (lane==bl) lv[mi] = -3.4e38f;
                if (lane==0) candv[ph][wi*8+it] = bm;
            }
        }
        __syncthreads();
        // stage 2: one warp per phase merges 128 candidates
        if ((warp & 15)==0){
            int ph = warp>>4;
            float lv[4];
            #pragma unroll
            for (int j=0;j<4;j++) lv[j] = candv[ph][j*32+lane];
            float kth_=0.f, smax_=0.f;
            #pragma unroll
            for (int it=0; it<TOPKK; ++it){
                float m=-3.4e38f; int mi=0;
                #pragma unroll
                for (int j=0;j<4;j++) if (lv[j]>m){ m=lv[j]; mi=j; }
                float bm=m; int bl=lane;
                #pragma unroll
                for (int o=16;o>0;o>>=1){
                    float om=__shfl_xor_sync(0xffffffffu,bm,o);
                    int   ol=__shfl_xor_sync(0xffffffffu,bl,o);
                    if (om>bm || (om==bm && ol<bl)){ bm=om; bl=ol; }
                }
                if (it==0) smax_=bm;
                if (it==TOPKK-1) kth_=bm;
                if (lane==bl) lv[mi] = -3.4e38f;
            }
            if (lane==0){ s_kth[ph]=kth_; s_smax[ph]=smax_; }
        }
        __syncthreads();

        // selection split 512/512 over phases
        {
            int ph = tid >> 9, lt = tid & 511;
            const float* sim = ph ? simw : simr;
            float kth = s_kth[ph], smax = s_smax[ph];
            float beta = ph ? beta_w : beta_r;
            #pragma unroll
            for (int j=0;j<4;j++){
                int i = j*512 + lt;
                float v = sim[i];
                if (v >= kth){
                    int p = atomicAdd(&s_cnt[ph], 1);
                    if (p < MAXSEL){ sel_idx[ph][p]=i; sel_w[ph][p]=expf(beta*(v-smax)); }
                }
            }
        }
        __syncthreads();
        if (tid < 2){
            int cnt = min(s_cnt[tid], MAXSEL);
            float ds=0.f;
            for (int j=0;j<cnt;j++) ds += sel_w[tid][j];
            s_inv[tid] = 1.0f/ds;
        }
        __syncthreads();

        // read gather (before write updates memory)
        {
            int cnt = min(s_cnt[0], MAXSEL);
            if (tid < HDD){
                float acc=0.f;
                float invd = s_inv[0];
                for (int j=0;j<cnt;j++)
                    acc += sel_w[0][j]*invd * g_mem[(((size_t)b*NN + sel_idx[0][j])*HMM + h)*HDD + tid];
                __stcg(&g_rvbuf[(t+1)&1][b*DD + h*HDD + tid], acc);
            }
        }
        __syncthreads();
        if (tid==0) red_release(&g_bar[b], 1u);   // release: orders stcg rv stores; no L1 flush

        // write update (block-private rows), 16-way row-parallel
        {
            int cnt = min(s_cnt[1], MAXSEL);
            float gg = sigmoid_f(gr_sh);
            int d = tid & 63;
            float ee = sigmoid_f(ifc_s[192 + d]);
            float gv = gg * ifc_s[128 + d];
            float invd = s_inv[1];
            for (int j = tid>>6; j<cnt; j+=16){
                float w = sel_w[1][j]*invd;
                size_t mi = (((size_t)b*NN + sel_idx[1][j])*HMM + h)*HDD + d;
                g_mem[mi] = g_mem[mi]*(1.0f - w*ee) + w*gv;
            }
        }
        __syncthreads();
        // refresh cached inverse norms for updated rows (one warp per row, 32 warps)
        {
            int cnt = min(s_cnt[1], MAXSEL);
            for (int j = warp; j < cnt; j += 32){
                int n = sel_idx[1][j];
                const float2* mrow = (const float2*)(g_mem + (((size_t)b*NN + n)*HMM + h)*HDD);
                float2 v = mrow[lane];
                float ss = v.x*v.x + v.y*v.y;
                #pragma unroll
                for (int o=16;o>0;o>>=1) ss += __shfl_xor_sync(0xffffffffu, ss, o);
                if (lane==0) g_norminv[((size_t)b*NN + n)*HMM + h] = rsqrtf(ss + 1e-8f);
            }
        }
        __syncthreads();

        if (tid==0){
            while (ld_acquire(&g_bar[b]) < (u32)HMM*(u32)(t+1)) { }
        }
        __syncthreads();
    }
}

extern "C" void kernel_launch(void* const* d_in, const int* in_sizes, int n_in,
                              void* d_out, int out_size)
{
    const int*   ids      = (const int*)  d_in[0];
    const float* emb      = (const float*)d_in[1];
    const float* pos      = (const float*)d_in[2];
    const float* ln1_g    = (const float*)d_in[3];
    const float* ln1_b    = (const float*)d_in[4];
    const float* ln2_g    = (const float*)d_in[5];
    const float* ln2_b    = (const float*)d_in[6];
    const float* Wq       = (const float*)d_in[7];
    const float* Wk       = (const float*)d_in[8];
    const float* Wv       = (const float*)d_in[9];
    const float* Wo       = (const float*)d_in[10];
    const float* W1       = (const float*)d_in[11];
    const float* b1       = (const float*)d_in[12];
    const float* W2       = (const float*)d_in[13];
    const float* b2       = (const float*)d_in[14];
    const float* lnf_g    = (const float*)d_in[15];
    const float* lnf_b    = (const float*)d_in[16];
    const float* W_if_h   = (const float*)d_in[17];
    const float* W_if_r   = (const float*)d_in[18];
    const float* b_if     = (const float*)d_in[19];
    const float* W_lg_h   = (const float*)d_in[20];
    const float* W_lg_r   = (const float*)d_in[21];
    const float* b_lg     = (const float*)d_in[22];
    const float* beta_read  = (const float*)d_in[23];
    const float* beta_write = (const float*)d_in[24];
    const float* mem_init = (const float*)d_in[25];
    float* out = (float*)d_out;

    float *px,*pq,*pk,*pv,*pif;
    u32 *pwh,*pwl,*pah,*pal,*pbh,*pbl;
    cudaGetSymbolAddress((void**)&px,  g_x);
    cudaGetSymbolAddress((void**)&pq,  g_q);
    cudaGetSymbolAddress((void**)&pk,  g_k);
    cudaGetSymbolAddress((void**)&pv,  g_v);
    cudaGetSymbolAddress((void**)&pif, g_iface);
    cudaGetSymbolAddress((void**)&pwh, g_wh);
    cudaGetSymbolAddress((void**)&pwl, g_wl);
    cudaGetSymbolAddress((void**)&pah, g_ah);
    cudaGetSymbolAddress((void**)&pal, g_al);
    cudaGetSymbolAddress((void**)&pbh, g_bh);
    cudaGetSymbolAddress((void**)&pbl, g_bl);

    const int M = BB*TT;

    embed_kernel<<<M,256>>>(ids, emb, pos);
    wsplit_kernel<<<dim3(2,512),256>>>(Wq, pwh+OFF_QKVO_W(0), pwl+OFF_QKVO_W(0), EE);
    wsplit_kernel<<<dim3(2,512),256>>>(Wk, pwh+OFF_QKVO_W(1), pwl+OFF_QKVO_W(1), EE);
    wsplit_kernel<<<dim3(2,512),256>>>(Wv, pwh+OFF_QKVO_W(2), pwl+OFF_QKVO_W(2), EE);

    for (int l=0; l<LL; ++l){
        ln_split_kernel<<<M,256>>>(px, ln1_g + l*EE, ln1_b + l*EE, pbh, pbl, 256);
        bgemm_kernel<false,false,false,false,false><<<dim3(4,16),256>>>(pbh, pbl, 256,
            pwh+OFF_QKVO_W(0)+l*131072, pwl+OFF_QKVO_W(0)+l*131072,
            nullptr, pq, nullptr, nullptr, 0, EE, 256);
        bgemm_kernel<false,false,false,false,false><<<dim3(4,16),256>>>(pbh, pbl, 256,
            pwh+OFF_QKVO_W(1)+l*131072, pwl+OFF_QKVO_W(1)+l*131072,
            nullptr, pk, nullptr, nullptr, 0, EE, 256);
        bgemm_kernel<false,false,false,false,false><<<dim3(4,16),256>>>(pbh, pbl, 256,
            pwh+OFF_QKVO_W(2)+l*131072, pwl+OFF_QKVO_W(2)+l*131072,
            nullptr, pv, nullptr, nullptr, 0, EE, 256);
        attn_s_kernel<<<dim3(64, BB*HAA),256>>>();
        softmax_kernel<<<BB*HAA*TT,256>>>();
        attn_o_kernel<<<dim3(8, BB*HAA),256>>>();
        if (l==0)
            wsplit_kernel<<<dim3(2,512),256>>>(Wo, pwh+OFF_QKVO_W(3), pwl+OFF_QKVO_W(3), EE);
        bgemm_kernel<true,false,false,false,false><<<dim3(4,16),256>>>(pbh, pbl, 256,
            pwh+OFF_QKVO_W(3)+l*131072, pwl+OFF_QKVO_W(3)+l*131072,
            nullptr, px, nullptr, nullptr, 0, EE, 256);
        ln_split_kernel<<<M,256>>>(px, ln2_g + l*EE, ln2_b + l*EE, pbh, pbl, 256);
        if (l==0){
            wsplit_kernel<<<dim3(8,512),256>>>(W1, pwh+OFF_W1, pwl+OFF_W1, FF);
            wsplit_kernel<<<dim3(2,2048),256>>>(W2, pwh+OFF_W2, pwl+OFF_W2, EE);
        }
        bgemm_kernel<false,true,true,false,true><<<dim3(16,16),256>>>(pbh, pbl, 256,
            pwh+OFF_W1+l*524288, pwl+OFF_W1+l*524288,
            b1 + l*FF, nullptr, pah, pal, 1024, FF, 256);
        bgemm_kernel<true,false,true,false,false><<<dim3(4,16),256>>>(pah, pal, 1024,
            pwh+OFF_W2+l*524288, pwl+OFF_W2+l*524288,
            b2 + l*EE, px, nullptr, nullptr, 0, EE, 1024);
    }

    // final LN -> vocab-A planes cols [0,256)
    ln_split_kernel<<<M,256>>>(px, lnf_g, lnf_b, pah, pal, 384);

    // iface = h @ W_if_h + b_if
    wsplit_kernel<<<dim3(5,256),256>>>(W_if_h, pwh+OFF_WIFH, pwl+OFF_WIFH, IFF);
    bgemm_kernel<false,false,true,true,false><<<dim3(9,16),256>>>(pah, pal, 384,
        pwh+OFF_WIFH, pwl+OFF_WIFH, b_if, pif, nullptr, nullptr, 0, IFF, 256);

    // vocab weight splits
    wsplit_kernel<<<dim3(125,256),256>>>(W_lg_h, pwh+OFF_WLG, pwl+OFF_WLG, VV);
    wsplit_kernel<<<dim3(125,128),256>>>(W_lg_r, pwh+OFF_WLG+(size_t)256*VV,
                                         pwl+OFF_WLG+(size_t)256*VV, VV);

    meminit_kernel<<<16384,256>>>(mem_init);
    norminit_kernel<<<BB*NN*HMM/8,256>>>();
    scaninit_kernel<<<8,256>>>();

    scan_persist_kernel<<<BB*HMM,1024>>>(W_if_r, beta_read, beta_write);

    // out = [h | rv] @ [W_lg_h ; W_lg_r] + b_lg
    bgemm_kernel<false,false,true,false,false><<<dim3(250,16),256>>>(pah, pal, 384,
        pwh+OFF_WLG, pwl+OFF_WLG, b_lg, out, nullptr, nullptr, 0, VV, 384);
}

// round 13
// speedup vs baseline: 1.1079x; 1.1079x over previous
#include <cuda_runtime.h>
#include <math.h>

typedef unsigned int u32;

#define BB 8
#define TT 256
#define EE 512
#define FF 2048
#define DD 256
#define NN 2048
#define LL 2
#define VV 32000
#define HMM 4
#define HDD 64
#define HAA 8
#define DHH 64
#define IFF 1028
#define TOPKK 8
#define MAXSEL 64

#define OFF_QKVO_W(w) ((w)*262144)
#define OFF_W1  1048576
#define OFF_W2  2097152
#define OFF_WIFH 3145728
#define OFF_WLG  3408896
#define ARENA    15696896

// ---- scratch ----
__device__ float g_x[BB*TT*EE];
__device__ float g_q[BB*TT*EE];
__device__ float g_k[BB*TT*EE];
__device__ float g_v[BB*TT*EE];
__device__ float g_s[BB*HAA*TT*TT];
__device__ float g_iface[BB*TT*IFF];
__device__ float g_mem[BB*NN*HMM*HDD];
__device__ float g_norminv[BB*NN*HMM];
__device__ float g_rvbuf[2][BB*DD];
__device__ u32   g_bar[BB];
__device__ u32   g_wh[ARENA];
__device__ u32   g_wl[ARENA];
__device__ u32   g_ah[2048*1024];
__device__ u32   g_al[2048*1024];
__device__ u32   g_bh[2048*256];
__device__ u32   g_bl[2048*256];

__device__ __forceinline__ float gelu_f(float x){
    float x3 = x*x*x;
    return 0.5f*x*(1.0f+tanhf(0.7978845608028654f*(x+0.044715f*x3)));
}
__device__ __forceinline__ float sigmoid_f(float x){ return 1.0f/(1.0f+expf(-x)); }
__device__ __forceinline__ float softplus_clip(float x){
    float sp = fmaxf(x,0.0f) + log1pf(expf(-fabsf(x)));
    return fminf(fmaxf(sp,1.0f),20.0f);
}

__device__ __forceinline__ void packpair(float e, float o, u32 &hi, u32 &lo){
    u32 h; asm("cvt.rn.bf16x2.f32 %0, %1, %2;" : "=r"(h) : "f"(o), "f"(e));
    float he = __uint_as_float(h<<16);
    float ho = __uint_as_float(h & 0xffff0000u);
    asm("cvt.rn.bf16x2.f32 %0, %1, %2;" : "=r"(lo) : "f"(o-ho), "f"(e-he));
    hi = h;
}

__device__ __forceinline__ void mma_bf16(float* c, const u32* a, const u32* b){
    asm volatile("mma.sync.aligned.m16n8k16.row.col.f32.bf16.bf16.f32 "
        "{%0,%1,%2,%3}, {%4,%5,%6,%7}, {%8,%9}, {%0,%1,%2,%3};\n"
        : "+f"(c[0]), "+f"(c[1]), "+f"(c[2]), "+f"(c[3])
        : "r"(a[0]), "r"(a[1]), "r"(a[2]), "r"(a[3]), "r"(b[0]), "r"(b[1]));
}

__device__ __forceinline__ u32 s2u(const void* p){ return (u32)__cvta_generic_to_shared(p); }
__device__ __forceinline__ void cp16(u32 d, const void* s){
    asm volatile("cp.async.cg.shared.global [%0], [%1], 16;\n"::"r"(d),"l"(s));
}
__device__ __forceinline__ void cp16z(u32 d, const void* s, int sz){
    asm volatile("cp.async.cg.shared.global [%0], [%1], 16, %2;\n"::"r"(d),"l"(s),"r"(sz));
}
__device__ __forceinline__ void cp_commit(){ asm volatile("cp.async.commit_group;\n"); }
__device__ __forceinline__ void cp_wait0(){ asm volatile("cp.async.wait_group 0;\n"); }

__device__ __forceinline__ void red_release(u32* p, u32 v){
    asm volatile("red.release.gpu.global.add.u32 [%0], %1;" :: "l"(p), "r"(v) : "memory");
}
__device__ __forceinline__ u32 ld_acquire(const u32* p){
    u32 v; asm volatile("ld.acquire.gpu.global.u32 %0, [%1];" : "=r"(v) : "l"(p) : "memory");
    return v;
}

// ---- weight split ----
__global__ void wsplit_kernel(const float* __restrict__ src, u32* __restrict__ dh,
                              u32* __restrict__ dl, int N){
    int k2 = blockIdx.y;
    int n = blockIdx.x*256 + threadIdx.x;
    if (n >= N) return;
    float e = src[(size_t)(2*k2)*N + n];
    float o = src[(size_t)(2*k2+1)*N + n];
    u32 hi, lo; packpair(e, o, hi, lo);
    dh[(size_t)k2*N + n] = hi;
    dl[(size_t)k2*N + n] = lo;
}

// ---- embedding ----
__global__ void embed_kernel(const int* __restrict__ ids,
                             const float* __restrict__ emb,
                             const float* __restrict__ pos){
    int bt = blockIdx.x;
    int t = bt & (TT-1);
    int id = ids[bt];
    for (int e = threadIdx.x; e < EE; e += 256)
        g_x[(size_t)bt*EE + e] = emb[(size_t)id*EE + e] + pos[(size_t)t*EE + e];
}

// ---- layernorm with split (plane) output ----
__global__ void ln_split_kernel(const float* __restrict__ x, const float* __restrict__ g,
                                const float* __restrict__ bb, u32* __restrict__ oh,
                                u32* __restrict__ ol, int lda2){
    int row = blockIdx.x, tid = threadIdx.x;
    __shared__ float red[256];
    const float* xr = x + (size_t)row*EE;
    float v0 = xr[2*tid], v1 = xr[2*tid+1];
    red[tid] = v0+v1; __syncthreads();
    for (int s=128;s>0;s>>=1){ if (tid<s) red[tid]+=red[tid+s]; __syncthreads(); }
    float m = red[0] * (1.0f/EE);
    __syncthreads();
    float d0=v0-m, d1=v1-m;
    red[tid] = d0*d0 + d1*d1; __syncthreads();
    for (int s=128;s>0;s>>=1){ if (tid<s) red[tid]+=red[tid+s]; __syncthreads(); }
    float rs = rsqrtf(red[0]*(1.0f/EE) + 1e-5f);
    float y0 = d0*rs*g[2*tid]   + bb[2*tid];
    float y1 = d1*rs*g[2*tid+1] + bb[2*tid+1];
    u32 hi, lo; packpair(y0, y1, hi, lo);
    oh[(size_t)row*lda2 + tid] = hi;
    ol[(size_t)row*lda2 + tid] = lo;
}

// ---- shared layouts for the mega kernel ----
struct GemmS {
    u32 AsH[2][128*12], AsL[2][128*12];
    u32 BsH[2][8][136], BsL[2][8][136];
};
struct ScanS {
    float rv[DD];
    float ifc[256];
    float pmat[4][256];
    float knr[HDD], knw[HDD];
    float simr[NN], simw[NN];
    float gr;
    float candv[2][32];
    float kth[2], smax[2];
    int   cnt[2];
    int   selidx[2][MAXSEL];
    float selw[2][MAXSEL];
    float sinv[2];
};

// GEMM tile body (device function), used by bgemm_kernel and mega_kernel
template<bool ACC, bool GELU, bool BIAS, bool NGUARD, bool OSPLIT>
__device__ __forceinline__ void gemm_tile(
    GemmS* sm, int bm, int bn,
    const u32* __restrict__ AH, const u32* __restrict__ AL, int lda2,
    const u32* __restrict__ BH, const u32* __restrict__ BL,
    const float* __restrict__ bias, float* __restrict__ C,
    u32* __restrict__ OH, u32* __restrict__ OL, int lda2o,
    int N, int K2)
{
    int tid = threadIdx.x;
    int warp = tid>>5, lane = tid&31;
    int wm = (warp>>2)*64, wn = (warp&3)*32;
    int gid = lane>>2, tig = lane&3;

    float c[4][4][4];
    #pragma unroll
    for (int mt=0;mt<4;mt++)
        #pragma unroll
        for (int nt=0;nt<4;nt++)
            #pragma unroll
            for (int i=0;i<4;i++) c[mt][nt][i]=0.f;

    int am = tid & 127, akp = (tid>>7)*4;
    int bk = tid>>5, bn4 = lane*4;
    const u32* AHp = AH + (size_t)(bm+am)*lda2 + akp;
    const u32* ALp = AL + (size_t)(bm+am)*lda2 + akp;
    int nit = K2/8;

    auto issueTile = [&](int buf, int it){
        cp16(s2u(&sm->AsH[buf][am*12+akp]), AHp + (size_t)it*8);
        cp16(s2u(&sm->AsL[buf][am*12+akp]), ALp + (size_t)it*8);
        int kr = it*8 + bk;
        const u32* ph_ = BH + (size_t)kr*N + bn + bn4;
        const u32* pl_ = BL + (size_t)kr*N + bn + bn4;
        if (!NGUARD){
            cp16(s2u(&sm->BsH[buf][bk][bn4]), ph_);
            cp16(s2u(&sm->BsL[buf][bk][bn4]), pl_);
        } else {
            int col = bn + bn4;
            int sz = (N - col)*4; sz = sz<0?0:(sz>16?16:sz);
            cp16z(s2u(&sm->BsH[buf][bk][bn4]), ph_, sz);
            cp16z(s2u(&sm->BsL[buf][bk][bn4]), pl_, sz);
        }
    };

    issueTile(0, 0); cp_commit();

    int cur = 0;
    for (int it=0; it<nit; ++it){
        cp_wait0();
        __syncthreads();
        if (it+1 < nit){ issueTile(cur^1, it+1); cp_commit(); }

        u32 aH[4][4], aL[4][4];
        #pragma unroll
        for (int mt=0;mt<4;mt++){
            int m0 = wm + mt*16 + gid;
            aH[mt][0]=sm->AsH[cur][m0*12     + tig  ]; aL[mt][0]=sm->AsL[cur][m0*12     + tig  ];
            aH[mt][1]=sm->AsH[cur][(m0+8)*12 + tig  ]; aL[mt][1]=sm->AsL[cur][(m0+8)*12 + tig  ];
            aH[mt][2]=sm->AsH[cur][m0*12     + tig+4]; aL[mt][2]=sm->AsL[cur][m0*12     + tig+4];
            aH[mt][3]=sm->AsH[cur][(m0+8)*12 + tig+4]; aL[mt][3]=sm->AsL[cur][(m0+8)*12 + tig+4];
        }
        u32 bH[4][2], bL[4][2];
        #pragma unroll
        for (int nt=0;nt<4;nt++){
            int n0 = wn + nt*8 + gid;
            bH[nt][0]=sm->BsH[cur][tig  ][n0]; bL[nt][0]=sm->BsL[cur][tig  ][n0];
            bH[nt][1]=sm->BsH[cur][tig+4][n0]; bL[nt][1]=sm->BsL[cur][tig+4][n0];
        }
        #pragma unroll
        for (int mt=0;mt<4;mt++){
            #pragma unroll
            for (int nt=0;nt<4;nt++){
                mma_bf16(c[mt][nt], aH[mt], bH[nt]);
                mma_bf16(c[mt][nt], aH[mt], bL[nt]);
                mma_bf16(c[mt][nt], aL[mt], bH[nt]);
            }
        }
        cur ^= 1;
    }

    #pragma unroll
    for (int mt=0;mt<4;mt++){
        int ra = bm + wm + mt*16 + gid;
        int rb = ra + 8;
        #pragma unroll
        for (int nt=0;nt<4;nt++){
            int col = bn + wn + nt*8 + tig*2;
            if (OSPLIT){
                float v0 = c[mt][nt][0], v1 = c[mt][nt][1];
                float v2 = c[mt][nt][2], v3 = c[mt][nt][3];
                if (BIAS){ float b0=bias[col], b1=bias[col+1]; v0+=b0; v1+=b1; v2+=b0; v3+=b1; }
                if (GELU){ v0=gelu_f(v0); v1=gelu_f(v1); v2=gelu_f(v2); v3=gelu_f(v3); }
                u32 hi, lo;
                packpair(v0, v1, hi, lo);
                OH[(size_t)ra*lda2o + (col>>1)] = hi; OL[(size_t)ra*lda2o + (col>>1)] = lo;
                packpair(v2, v3, hi, lo);
                OH[(size_t)rb*lda2o + (col>>1)] = hi; OL[(size_t)rb*lda2o + (col>>1)] = lo;
            } else {
                #pragma unroll
                for (int q=0;q<4;q++){
                    int r = (q<2)? ra : rb;
                    int cc = col + (q&1);
                    if (NGUARD && cc >= N) continue;
                    float v = c[mt][nt][q];
                    if (BIAS) v += bias[cc];
                    if (GELU) v = gelu_f(v);
                    size_t idx = (size_t)r*N + cc;
                    if (ACC) v += C[idx];
                    C[idx] = v;
                }
            }
        }
    }
}

template<bool ACC, bool GELU, bool BIAS, bool NGUARD, bool OSPLIT>
__global__ __launch_bounds__(256)
void bgemm_kernel(const u32* __restrict__ AH, const u32* __restrict__ AL, int lda2,
                  const u32* __restrict__ BH, const u32* __restrict__ BL,
                  const float* __restrict__ bias, float* __restrict__ C,
                  u32* __restrict__ OH, u32* __restrict__ OL, int lda2o,
                  int N, int K2)
{
    __shared__ GemmS sm;
    gemm_tile<ACC,GELU,BIAS,NGUARD,OSPLIT>(&sm, blockIdx.y*128, blockIdx.x*128,
        AH, AL, lda2, BH, BL, bias, C, OH, OL, lda2o, N, K2);
}

// ---- attention ----
__global__ void attn_s_kernel(){
    int bh = blockIdx.y;
    int b = bh >> 3, h = bh & 7;
    int qt = blockIdx.x >> 3, kt = blockIdx.x & 7;
    __shared__ float Qs[32][65];
    __shared__ float Ks[32][65];
    int tid = threadIdx.x;
    {
        int r = tid >> 3, cc = (tid & 7)*8;
        const float* qsrc = g_q + ((size_t)(b*TT + qt*32 + r))*EE + h*DHH + cc;
        const float* ksrc = g_k + ((size_t)(b*TT + kt*32 + r))*EE + h*DHH + cc;
        float4 q0 = *(const float4*)qsrc, q1 = *(const float4*)(qsrc+4);
        float4 k0 = *(const float4*)ksrc, k1 = *(const float4*)(ksrc+4);
        Qs[r][cc+0]=q0.x; Qs[r][cc+1]=q0.y; Qs[r][cc+2]=q0.z; Qs[r][cc+3]=q0.w;
        Qs[r][cc+4]=q1.x; Qs[r][cc+5]=q1.y; Qs[r][cc+6]=q1.z; Qs[r][cc+7]=q1.w;
        Ks[r][cc+0]=k0.x; Ks[r][cc+1]=k0.y; Ks[r][cc+2]=k0.z; Ks[r][cc+3]=k0.w;
        Ks[r][cc+4]=k1.x; Ks[r][cc+5]=k1.y; Ks[r][cc+6]=k1.z; Ks[r][cc+7]=k1.w;
    }
    __syncthreads();
    int r = tid & 31, gq = tid >> 5;
    float a0=0,a1=0,a2=0,a3=0;
    #pragma unroll
    for (int kk=0;kk<64;kk++){
        float qv = Qs[r][kk];
        a0 += qv*Ks[gq*4+0][kk];
        a1 += qv*Ks[gq*4+1][kk];
        a2 += qv*Ks[gq*4+2][kk];
        a3 += qv*Ks[gq*4+3][kk];
    }
    int qrow = qt*32 + r;
    int kc = kt*32 + gq*4;
    float* srow = g_s + ((size_t)bh*TT + qrow)*TT + kc;
    srow[0] = (kc+0<=qrow)? a0*0.125f : -1e30f;
    srow[1] = (kc+1<=qrow)? a1*0.125f : -1e30f;
    srow[2] = (kc+2<=qrow)? a2*0.125f : -1e30f;
    srow[3] = (kc+3<=qrow)? a3*0.125f : -1e30f;
}

__global__ void softmax_kernel(){
    int row = blockIdx.x, tid = threadIdx.x;
    __shared__ float red[256];
    float* sp = g_s + (size_t)row*TT;
    float v = sp[tid];
    red[tid]=v; __syncthreads();
    for (int s=128;s>0;s>>=1){ if (tid<s) red[tid]=fmaxf(red[tid],red[tid+s]); __syncthreads(); }
    float m = red[0]; __syncthreads();
    float e = expf(v-m);
    red[tid]=e; __syncthreads();
    for (int s=128;s>0;s>>=1){ if (tid<s) red[tid]+=red[tid+s]; __syncthreads(); }
    sp[tid] = e / red[0];
}

__global__ void attn_o_kernel(){
    int bh = blockIdx.y;
    int b = bh >> 3, h = bh & 7;
    int qt = blockIdx.x;
    __shared__ float As[32][65];
    __shared__ float Vs[64][64];
    int tid = threadIdx.x;
    int d = tid & 63, qg = tid >> 6;
    float acc[8];
    #pragma unroll
    for (int i=0;i<8;i++) acc[i]=0.f;
    for (int k0=0;k0<TT;k0+=64){
        {
            int r = tid >> 3, cc = (tid & 7)*8;
            const float* src = g_s + ((size_t)bh*TT + qt*32 + r)*TT + k0 + cc;
            float4 a0=*(const float4*)src, a1=*(const float4*)(src+4);
            As[r][cc+0]=a0.x; As[r][cc+1]=a0.y; As[r][cc+2]=a0.z; As[r][cc+3]=a0.w;
            As[r][cc+4]=a1.x; As[r][cc+5]=a1.y; As[r][cc+6]=a1.z; As[r][cc+7]=a1.w;
        }
        #pragma unroll
        for (int i=0;i<4;i++){
            int fl = (tid + 256*i)*4;
            int r = fl >> 6, cc = fl & 63;
            float4 vv = *(const float4*)(g_v + ((size_t)(b*TT + k0 + r))*EE + h*DHH + cc);
            *(float4*)&Vs[r][cc] = vv;
        }
        __syncthreads();
        #pragma unroll
        for (int kk=0;kk<64;kk++){
            float vv = Vs[kk][d];
            #pragma unroll
            for (int i=0;i<8;i++) acc[i] += As[qg*8+i][kk]*vv;
        }
        __syncthreads();
    }
    #pragma unroll
    for (int i=0;i<8;i++){
        int qr = qt*32 + qg*8 + i;
        float other = __shfl_xor_sync(0xffffffffu, acc[i], 1);
        if ((d & 1) == 0){
            u32 hi, lo; packpair(acc[i], other, hi, lo);
            int pc = (h*DHH + d) >> 1;
            size_t row = (size_t)(b*TT + qr);
            g_bh[row*256 + pc] = hi;
            g_bl[row*256 + pc] = lo;
        }
    }
}

// ---- init ----
__global__ void meminit_kernel(const float* __restrict__ mi){
    int idx = blockIdx.x*256 + threadIdx.x;
    g_mem[idx] = mi[idx & (NN*DD - 1)];
}
__global__ void norminit_kernel(){
    int gw = blockIdx.x*8 + (threadIdx.x>>5);
    int lane = threadIdx.x & 31;
    const float2* mrow = (const float2*)(g_mem + (size_t)gw*HDD);
    float2 v = mrow[lane];
    float ss = v.x*v.x + v.y*v.y;
    #pragma unroll
    for (int o=16;o>0;o>>=1) ss += __shfl_xor_sync(0xffffffffu, ss, o);
    if (lane==0) g_norminv[gw] = rsqrtf(ss + 1e-8f);
}
__global__ void scaninit_kernel(){
    int i = blockIdx.x*256 + threadIdx.x;
    g_rvbuf[0][i] = 0.f;
    if (i < BB) g_bar[i] = 0u;
}

// ---- scan body (R9 version, 256 threads, block-private) ----
__device__ void scan_body(ScanS* sp_, const float* __restrict__ Wr,
                          const float* __restrict__ pbr, const float* __restrict__ pbw)
{
    int bh = blockIdx.x;
    int b = bh >> 2, h = bh & 3;
    int tid = threadIdx.x, warp = tid>>5, lane = tid&31;
    ScanS& S = *sp_;

    float beta_r = softplus_clip(*pbr);
    float beta_w = softplus_clip(*pbw);

    for (int t=0; t<TT; ++t){
        S.rv[tid] = __ldcg(&g_rvbuf[t&1][b*DD + tid]);
        if (tid==0){ S.cnt[0]=0; S.cnt[1]=0; }
        __syncthreads();
        if (h == 0 && tid < 128){
            u32 hi, lo; packpair(S.rv[2*tid], S.rv[2*tid+1], hi, lo);
            size_t row = (size_t)(b*TT + t);
            g_ah[row*384 + 256 + tid] = hi;
            g_al[row*384 + 256 + tid] = lo;
        }

        // iface matvec: float4 loads, 4-way d-split
        {
            int cq = tid & 63, dg = tid >> 6;
            int seg = cq >> 4, cl4 = (cq & 15)*4;
            int col = seg*DD + h*HDD + cl4;
            const float* wp = Wr + (size_t)(dg*64)*IFF + col;
            float ax=0.f, ay=0.f, az=0.f, aw=0.f;
            #pragma unroll 8
            for (int d=0; d<64; ++d){
                float r = S.rv[dg*64 + d];
                float4 w = *reinterpret_cast<const float4*>(wp + (size_t)d*IFF);
                ax += r*w.x; ay += r*w.y; az += r*w.z; aw += r*w.w;
            }
            int p = seg*64 + cl4;
            S.pmat[dg][p+0]=ax; S.pmat[dg][p+1]=ay; S.pmat[dg][p+2]=az; S.pmat[dg][p+3]=aw;
        }
        if (tid < 32){
            int col = 4*DD + h;
            float acc = 0.f;
            for (int d=tid; d<DD; d+=32) acc += S.rv[d]*Wr[(size_t)d*IFF + col];
            #pragma unroll
            for (int o=16;o>0;o>>=1) acc += __shfl_xor_sync(0xffffffffu, acc, o);
            if (tid==0) S.gr = acc + g_iface[(size_t)(b*TT + t)*IFF + col];
        }
        __syncthreads();
        {
            int grp = tid >> 6, l = tid & 63;
            int col = grp*DD + h*HDD + l;
            S.ifc[tid] = g_iface[(size_t)(b*TT + t)*IFF + col]
                       + S.pmat[0][tid] + S.pmat[1][tid] + S.pmat[2][tid] + S.pmat[3][tid];
        }
        __syncthreads();

        if (tid < 64){
            int w = tid >> 5, l = tid & 31;
            float v0 = S.ifc[w*64 + l], v1 = S.ifc[w*64 + l + 32];
            float ss = v0*v0 + v1*v1;
            #pragma unroll
            for (int o=16;o>0;o>>=1) ss += __shfl_xor_sync(0xffffffffu, ss, o);
            float rn = rsqrtf(ss + 1e-8f);
            float* dst = w ? S.knw : S.knr;
            dst[l] = v0*rn; dst[l+32] = v1*rn;
        }
        __syncthreads();

        // sims: one thread per row, cached inverse norms
        for (int j=0;j<8;j++){
            int n = j*256 + tid;
            const float4* mrow = (const float4*)(g_mem + (((size_t)b*NN + n)*HMM + h)*HDD);
            float dr=0.f, dw=0.f;
            #pragma unroll
            for (int c2=0;c2<16;c2++){
                float4 m  = mrow[c2];
                float4 kr = *(const float4*)&S.knr[c2*4];
                float4 kw = *(const float4*)&S.knw[c2*4];
                dr += m.x*kr.x + m.y*kr.y + m.z*kr.z + m.w*kr.w;
                dw += m.x*kw.x + m.y*kw.y + m.z*kw.z + m.w*kw.w;
            }
            float ninv = g_norminv[((size_t)b*NN + n)*HMM + h];
            S.simr[n] = dr*ninv;
            S.simw[n] = dw*ninv;
        }
        __syncthreads();

        // warp-parallel topk: warps 0-3 read, 4-7 write
        {
            int ph = warp >> 2, wi = warp & 3;
            const float* sim = ph ? S.simw : S.simr;
            float lv[16];
            #pragma unroll
            for (int j=0;j<16;j++) lv[j] = sim[wi*512 + j*32 + lane];
            #pragma unroll
            for (int it=0; it<TOPKK; ++it){
                float m=-3.4e38f; int mi=0;
                #pragma unroll
                for (int j=0;j<16;j++) if (lv[j]>m){ m=lv[j]; mi=j; }
                float bm=m; int bl=lane;
                #pragma unroll
                for (int o=16;o>0;o>>=1){
                    float om=__shfl_xor_sync(0xffffffffu,bm,o);
                    int   ol=__shfl_xor_sync(0xffffffffu,bl,o);
                    if (om>bm || (om==bm && ol<bl)){ bm=om; bl=ol; }
                }
                if (lane==bl) lv[mi] = -3.4e38f;
                if (lane==0) S.candv[ph][wi*8+it] = bm;
            }
        }
        __syncthreads();
        if ((warp&3)==0){
            int ph = warp>>2;
            float v = S.candv[ph][lane];
            float kth_=0.f, smax_=0.f;
            #pragma unroll
            for (int it=0; it<TOPKK; ++it){
                float bm=v; int bl=lane;
                #pragma unroll
                for (int o=16;o>0;o>>=1){
                    float om=__shfl_xor_sync(0xffffffffu,bm,o);
                    int   ol=__shfl_xor_sync(0xffffffffu,bl,o);
                    if (om>bm || (om==bm && ol<bl)){ bm=om; bl=ol; }
                }
                if (it==0) smax_=bm;
                if (it==TOPKK-1) kth_=bm;
                if (lane==bl) v = -3.4e38f;
            }
            if (lane==0){ S.kth[ph]=kth_; S.smax[ph]=smax_; }
        }
        __syncthreads();

        {
            int ph = tid >> 7, lt = tid & 127;
            const float* sim = ph ? S.simw : S.simr;
            float kth = S.kth[ph], smax = S.smax[ph];
            float beta = ph ? beta_w : beta_r;
            #pragma unroll
            for (int j=0;j<16;j++){
                int i = j*128 + lt;
                float v = sim[i];
                if (v >= kth){
                    int p = atomicAdd(&S.cnt[ph], 1);
                    if (p < MAXSEL){ S.selidx[ph][p]=i; S.selw[ph][p]=expf(beta*(v-smax)); }
                }
            }
        }
        __syncthreads();
        if (tid < 2){
            int cnt = min(S.cnt[tid], MAXSEL);
            float ds=0.f;
            for (int j=0;j<cnt;j++) ds += S.selw[tid][j];
            S.sinv[tid] = 1.0f/ds;
        }
        __syncthreads();

        {
            int cnt = min(S.cnt[0], MAXSEL);
            if (tid < HDD){
                float acc=0.f;
                float invd = S.sinv[0];
                for (int j=0;j<cnt;j++)
                    acc += S.selw[0][j]*invd * g_mem[(((size_t)b*NN + S.selidx[0][j])*HMM + h)*HDD + tid];
                __stcg(&g_rvbuf[(t+1)&1][b*DD + h*HDD + tid], acc);
            }
        }
        __syncthreads();
        if (tid==0) red_release(&g_bar[b], 1u);

        {
            int cnt = min(S.cnt[1], MAXSEL);
            float gg = sigmoid_f(S.gr);
            int d = tid & 63;
            float ee = sigmoid_f(S.ifc[192 + d]);
            float gv = gg * S.ifc[128 + d];
            float invd = S.sinv[1];
            for (int j = tid>>6; j<cnt; j+=4){
                float w = S.selw[1][j]*invd;
                size_t mi = (((size_t)b*NN + S.selidx[1][j])*HMM + h)*HDD + d;
                g_mem[mi] = g_mem[mi]*(1.0f - w*ee) + w*gv;
            }
        }
        __syncthreads();
        {
            int cnt = min(S.cnt[1], MAXSEL);
            for (int j = warp; j < cnt; j += 8){
                int n = S.selidx[1][j];
                const float2* mrow = (const float2*)(g_mem + (((size_t)b*NN + n)*HMM + h)*HDD);
                float2 v = mrow[lane];
                float ss = v.x*v.x + v.y*v.y;
                #pragma unroll
                for (int o=16;o>0;o>>=1) ss += __shfl_xor_sync(0xffffffffu, ss, o);
                if (lane==0) g_norminv[((size_t)b*NN + n)*HMM + h] = rsqrtf(ss + 1e-8f);
            }
        }
        __syncthreads();

        if (tid==0){
            while (ld_acquire(&g_bar[b]) < (u32)HMM*(u32)(t+1)) { }
        }
        __syncthreads();
    }
}

// ---- mega kernel: blocks 0-31 = persistent scan, blocks 32+ = vocab-h GEMM tiles ----
__global__ __launch_bounds__(256)
void mega_kernel(const float* __restrict__ Wr,
                 const float* __restrict__ pbr,
                 const float* __restrict__ pbw,
                 const float* __restrict__ b_lg,
                 float* __restrict__ out)
{
    __shared__ __align__(16) char smraw[sizeof(GemmS)];
    if (blockIdx.x < 32){
        scan_body((ScanS*)smraw, Wr, pbr, pbw);
    } else {
        int tile = blockIdx.x - 32;          // 0..3999
        int bn = (tile % 250)*128;
        int bm = (tile / 250)*128;
        // out = h @ W_lg_h + b_lg  (h-part of the vocab GEMM, K2=256)
        gemm_tile<false,false,true,false,false>((GemmS*)smraw, bm, bn,
            g_ah, g_al, 384, g_wh + OFF_WLG, g_wl + OFF_WLG,
            b_lg, out, nullptr, nullptr, 0, VV, 256);
    }
}

extern "C" void kernel_launch(void* const* d_in, const int* in_sizes, int n_in,
                              void* d_out, int out_size)
{
    const int*   ids      = (const int*)  d_in[0];
    const float* emb      = (const float*)d_in[1];
    const float* pos      = (const float*)d_in[2];
    const float* ln1_g    = (const float*)d_in[3];
    const float* ln1_b    = (const float*)d_in[4];
    const float* ln2_g    = (const float*)d_in[5];
    const float* ln2_b    = (const float*)d_in[6];
    const float* Wq       = (const float*)d_in[7];
    const float* Wk       = (const float*)d_in[8];
    const float* Wv       = (const float*)d_in[9];
    const float* Wo       = (const float*)d_in[10];
    const float* W1       = (const float*)d_in[11];
    const float* b1       = (const float*)d_in[12];
    const float* W2       = (const float*)d_in[13];
    const float* b2       = (const float*)d_in[14];
    const float* lnf_g    = (const float*)d_in[15];
    const float* lnf_b    = (const float*)d_in[16];
    const float* W_if_h   = (const float*)d_in[17];
    const float* W_if_r   = (const float*)d_in[18];
    const float* b_if     = (const float*)d_in[19];
    const float* W_lg_h   = (const float*)d_in[20];
    const float* W_lg_r   = (const float*)d_in[21];
    const float* b_lg     = (const float*)d_in[22];
    const float* beta_read  = (const float*)d_in[23];
    const float* beta_write = (const float*)d_in[24];
    const float* mem_init = (const float*)d_in[25];
    float* out = (float*)d_out;

    float *px,*pq,*pk,*pv,*pif;
    u32 *pwh,*pwl,*pah,*pal,*pbh,*pbl;
    cudaGetSymbolAddress((void**)&px,  g_x);
    cudaGetSymbolAddress((void**)&pq,  g_q);
    cudaGetSymbolAddress((void**)&pk,  g_k);
    cudaGetSymbolAddress((void**)&pv,  g_v);
    cudaGetSymbolAddress((void**)&pif, g_iface);
    cudaGetSymbolAddress((void**)&pwh, g_wh);
    cudaGetSymbolAddress((void**)&pwl, g_wl);
    cudaGetSymbolAddress((void**)&pah, g_ah);
    cudaGetSymbolAddress((void**)&pal, g_al);
    cudaGetSymbolAddress((void**)&pbh, g_bh);
    cudaGetSymbolAddress((void**)&pbl, g_bl);

    const int M = BB*TT;

    embed_kernel<<<M,256>>>(ids, emb, pos);
    wsplit_kernel<<<dim3(2,512),256>>>(Wq, pwh+OFF_QKVO_W(0), pwl+OFF_QKVO_W(0), EE);
    wsplit_kernel<<<dim3(2,512),256>>>(Wk, pwh+OFF_QKVO_W(1), pwl+OFF_QKVO_W(1), EE);
    wsplit_kernel<<<dim3(2,512),256>>>(Wv, pwh+OFF_QKVO_W(2), pwl+OFF_QKVO_W(2), EE);

    for (int l=0; l<LL; ++l){
        ln_split_kernel<<<M,256>>>(px, ln1_g + l*EE, ln1_b + l*EE, pbh, pbl, 256);
        bgemm_kernel<false,false,false,false,false><<<dim3(4,16),256>>>(pbh, pbl, 256,
            pwh+OFF_QKVO_W(0)+l*131072, pwl+OFF_QKVO_W(0)+l*131072,
            nullptr, pq, nullptr, nullptr, 0, EE, 256);
        bgemm_kernel<false,false,false,false,false><<<dim3(4,16),256>>>(pbh, pbl, 256,
            pwh+OFF_QKVO_W(1)+l*131072, pwl+OFF_QKVO_W(1)+l*131072,
            nullptr, pk, nullptr, nullptr, 0, EE, 256);
        bgemm_kernel<false,false,false,false,false><<<dim3(4,16),256>>>(pbh, pbl, 256,
            pwh+OFF_QKVO_W(2)+l*131072, pwl+OFF_QKVO_W(2)+l*131072,
            nullptr, pv, nullptr, nullptr, 0, EE, 256);
        attn_s_kernel<<<dim3(64, BB*HAA),256>>>();
        softmax_kernel<<<BB*HAA*TT,256>>>();
        attn_o_kernel<<<dim3(8, BB*HAA),256>>>();
        if (l==0)
            wsplit_kernel<<<dim3(2,512),256>>>(Wo, pwh+OFF_QKVO_W(3), pwl+OFF_QKVO_W(3), EE);
        bgemm_kernel<true,false,false,false,false><<<dim3(4,16),256>>>(pbh, pbl, 256,
            pwh+OFF_QKVO_W(3)+l*131072, pwl+OFF_QKVO_W(3)+l*131072,
            nullptr, px, nullptr, nullptr, 0, EE, 256);
        ln_split_kernel<<<M,256>>>(px, ln2_g + l*EE, ln2_b + l*EE, pbh, pbl, 256);
        if (l==0){
            wsplit_kernel<<<dim3(8,512),256>>>(W1, pwh+OFF_W1, pwl+OFF_W1, FF);
            wsplit_kernel<<<dim3(2,2048),256>>>(W2, pwh+OFF_W2, pwl+OFF_W2, EE);
        }
        bgemm_kernel<false,true,true,false,true><<<dim3(16,16),256>>>(pbh, pbl, 256,
            pwh+OFF_W1+l*524288, pwl+OFF_W1+l*524288,
            b1 + l*FF, nullptr, pah, pal, 1024, FF, 256);
        bgemm_kernel<true,false,true,false,false><<<dim3(4,16),256>>>(pah, pal, 1024,
            pwh+OFF_W2+l*524288, pwl+OFF_W2+l*524288,
            b2 + l*EE, px, nullptr, nullptr, 0, EE, 1024);
    }

    // final LN -> vocab-A planes cols [0,256)
    ln_split_kernel<<<M,256>>>(px, lnf_g, lnf_b, pah, pal, 384);

    // iface = h @ W_if_h + b_if
    wsplit_kernel<<<dim3(5,256),256>>>(W_if_h, pwh+OFF_WIFH, pwl+OFF_WIFH, IFF);
    bgemm_kernel<false,false,true,true,false><<<dim3(9,16),256>>>(pah, pal, 384,
        pwh+OFF_WIFH, pwl+OFF_WIFH, b_if, pif, nullptr, nullptr, 0, IFF, 256);

    // vocab weight splits (must precede mega kernel: GEMM half reads W_lg_h planes)
    wsplit_kernel<<<dim3(125,256),256>>>(W_lg_h, pwh+OFF_WLG, pwl+OFF_WLG, VV);
    wsplit_kernel<<<dim3(125,128),256>>>(W_lg_r, pwh+OFF_WLG+(size_t)256*VV,
                                         pwl+OFF_WLG+(size_t)256*VV, VV);

    meminit_kernel<<<16384,256>>>(mem_init);
    norminit_kernel<<<BB*NN*HMM/8,256>>>();
    scaninit_kernel<<<8,256>>>();

    // mega: scan (blocks 0-31) overlapped with vocab-h GEMM (blocks 32..4031)
    mega_kernel<<<32 + 4000, 256>>>(W_if_r, beta_read, beta_write, b_lg, out);

    // out += rv_carry @ W_lg_r   (K2=128, A cols 256..383)
    bgemm_kernel<true,false,false,false,false><<<dim3(250,16),256>>>(pah + 256, pal + 256, 384,
        pwh+OFF_WLG+(size_t)256*VV, pwl+OFF_WLG+(size_t)256*VV,
        nullptr, out, nullptr, nullptr, 0, VV, 128);
}

// round 16
// speedup vs baseline: 1.1283x; 1.0184x over previous
#include <cuda_runtime.h>
#include <math.h>

typedef unsigned int u32;

#define BB 8
#define TT 256
#define EE 512
#define FF 2048
#define DD 256
#define NN 2048
#define LL 2
#define VV 32000
#define HMM 4
#define HDD 64
#define HAA 8
#define DHH 64
#define IFF 1028
#define TOPKK 8
#define MAXSEL 64

#define OFF_QKVO_W(w) ((w)*262144)
#define OFF_W1  1048576
#define OFF_W2  2097152
#define OFF_WIFH 3145728
#define OFF_WLG  3408896
#define ARENA    15696896

// ---- scratch ----
__device__ float g_x[BB*TT*EE];
__device__ float g_q[BB*TT*EE];
__device__ float g_k[BB*TT*EE];
__device__ float g_v[BB*TT*EE];
__device__ float g_s[BB*HAA*TT*TT];
__device__ float g_iface[BB*TT*IFF];
__device__ float g_mem[BB*NN*HMM*HDD];
__device__ float g_norminv[BB*NN*HMM];
__device__ float g_rvbuf[2][BB*DD];
__device__ u32   g_bar[BB];
__device__ u32   g_hdone;
__device__ u32   g_wh[ARENA];
__device__ u32   g_wl[ARENA];
__device__ u32   g_ah[2048*1024];
__device__ u32   g_al[2048*1024];
__device__ u32   g_bh[2048*256];
__device__ u32   g_bl[2048*256];

__device__ __forceinline__ float gelu_f(float x){
    float x3 = x*x*x;
    return 0.5f*x*(1.0f+tanhf(0.7978845608028654f*(x+0.044715f*x3)));
}
__device__ __forceinline__ float sigmoid_f(float x){ return 1.0f/(1.0f+expf(-x)); }
__device__ __forceinline__ float softplus_clip(float x){
    float sp = fmaxf(x,0.0f) + log1pf(expf(-fabsf(x)));
    return fminf(fmaxf(sp,1.0f),20.0f);
}

__device__ __forceinline__ void packpair(float e, float o, u32 &hi, u32 &lo){
    u32 h; asm("cvt.rn.bf16x2.f32 %0, %1, %2;" : "=r"(h) : "f"(o), "f"(e));
    float he = __uint_as_float(h<<16);
    float ho = __uint_as_float(h & 0xffff0000u);
    asm("cvt.rn.bf16x2.f32 %0, %1, %2;" : "=r"(lo) : "f"(o-ho), "f"(e-he));
    hi = h;
}

__device__ __forceinline__ void mma_bf16(float* c, const u32* a, const u32* b){
    asm volatile("mma.sync.aligned.m16n8k16.row.col.f32.bf16.bf16.f32 "
        "{%0,%1,%2,%3}, {%4,%5,%6,%7}, {%8,%9}, {%0,%1,%2,%3};\n"
        : "+f"(c[0]), "+f"(c[1]), "+f"(c[2]), "+f"(c[3])
        : "r"(a[0]), "r"(a[1]), "r"(a[2]), "r"(a[3]), "r"(b[0]), "r"(b[1]));
}

__device__ __forceinline__ u32 s2u(const void* p){ return (u32)__cvta_generic_to_shared(p); }
__device__ __forceinline__ void cp16(u32 d, const void* s){
    asm volatile("cp.async.cg.shared.global [%0], [%1], 16;\n"::"r"(d),"l"(s));
}
__device__ __forceinline__ void cp16z(u32 d, const void* s, int sz){
    asm volatile("cp.async.cg.shared.global [%0], [%1], 16, %2;\n"::"r"(d),"l"(s),"r"(sz));
}
__device__ __forceinline__ void cp_commit(){ asm volatile("cp.async.commit_group;\n"); }
__device__ __forceinline__ void cp_wait0(){ asm volatile("cp.async.wait_group 0;\n"); }

__device__ __forceinline__ void red_release(u32* p, u32 v){
    asm volatile("red.release.gpu.global.add.u32 [%0], %1;" :: "l"(p), "r"(v) : "memory");
}
__device__ __forceinline__ u32 ld_acquire(const u32* p){
    u32 v; asm volatile("ld.acquire.gpu.global.u32 %0, [%1];" : "=r"(v) : "l"(p) : "memory");
    return v;
}

// ---- weight split ----
__global__ void wsplit_kernel(const float* __restrict__ src, u32* __restrict__ dh,
                              u32* __restrict__ dl, int N){
    int k2 = blockIdx.y;
    int n = blockIdx.x*256 + threadIdx.x;
    if (n >= N) return;
    float e = src[(size_t)(2*k2)*N + n];
    float o = src[(size_t)(2*k2+1)*N + n];
    u32 hi, lo; packpair(e, o, hi, lo);
    dh[(size_t)k2*N + n] = hi;
    dl[(size_t)k2*N + n] = lo;
}

// ---- embedding ----
__global__ void embed_kernel(const int* __restrict__ ids,
                             const float* __restrict__ emb,
                             const float* __restrict__ pos){
    int bt = blockIdx.x;
    int t = bt & (TT-1);
    int id = ids[bt];
    for (int e = threadIdx.x; e < EE; e += 256)
        g_x[(size_t)bt*EE + e] = emb[(size_t)id*EE + e] + pos[(size_t)t*EE + e];
}

// ---- layernorm with split (plane) output ----
__global__ void ln_split_kernel(const float* __restrict__ x, const float* __restrict__ g,
                                const float* __restrict__ bb, u32* __restrict__ oh,
                                u32* __restrict__ ol, int lda2){
    int row = blockIdx.x, tid = threadIdx.x;
    __shared__ float red[256];
    const float* xr = x + (size_t)row*EE;
    float v0 = xr[2*tid], v1 = xr[2*tid+1];
    red[tid] = v0+v1; __syncthreads();
    for (int s=128;s>0;s>>=1){ if (tid<s) red[tid]+=red[tid+s]; __syncthreads(); }
    float m = red[0] * (1.0f/EE);
    __syncthreads();
    float d0=v0-m, d1=v1-m;
    red[tid] = d0*d0 + d1*d1; __syncthreads();
    for (int s=128;s>0;s>>=1){ if (tid<s) red[tid]+=red[tid+s]; __syncthreads(); }
    float rs = rsqrtf(red[0]*(1.0f/EE) + 1e-5f);
    float y0 = d0*rs*g[2*tid]   + bb[2*tid];
    float y1 = d1*rs*g[2*tid+1] + bb[2*tid+1];
    u32 hi, lo; packpair(y0, y1, hi, lo);
    oh[(size_t)row*lda2 + tid] = hi;
    ol[(size_t)row*lda2 + tid] = lo;
}

// ---- shared layouts ----
struct GemmS {
    u32 AsH[2][128*12], AsL[2][128*12];
    u32 BsH[2][8][136], BsL[2][8][136];
};
struct ScanS {
    float rv[DD];
    float ifc[256];
    float pmat[4][256];
    float knr[HDD], knw[HDD];
    float simr[NN], simw[NN];
    float gr;
    float candv[2][32];
    float kth[2], smax[2];
    int   cnt[2];
    int   selidx[2][MAXSEL];
    float selw[2][MAXSEL];
    float sinv[2];
};

// GEMM tile body
template<bool ACC, bool GELU, bool BIAS, bool NGUARD, bool OSPLIT>
__device__ __forceinline__ void gemm_tile(
    GemmS* sm, int bm, int bn,
    const u32* __restrict__ AH, const u32* __restrict__ AL, int lda2,
    const u32* __restrict__ BH, const u32* __restrict__ BL,
    const float* __restrict__ bias, float* __restrict__ C,
    u32* __restrict__ OH, u32* __restrict__ OL, int lda2o,
    int N, int K2)
{
    int tid = threadIdx.x;
    int warp = tid>>5, lane = tid&31;
    int wm = (warp>>2)*64, wn = (warp&3)*32;
    int gid = lane>>2, tig = lane&3;

    float c[4][4][4];
    #pragma unroll
    for (int mt=0;mt<4;mt++)
        #pragma unroll
        for (int nt=0;nt<4;nt++)
            #pragma unroll
            for (int i=0;i<4;i++) c[mt][nt][i]=0.f;

    int am = tid & 127, akp = (tid>>7)*4;
    int bk = tid>>5, bn4 = lane*4;
    const u32* AHp = AH + (size_t)(bm+am)*lda2 + akp;
    const u32* ALp = AL + (size_t)(bm+am)*lda2 + akp;
    int nit = K2/8;

    auto issueTile = [&](int buf, int it){
        cp16(s2u(&sm->AsH[buf][am*12+akp]), AHp + (size_t)it*8);
        cp16(s2u(&sm->AsL[buf][am*12+akp]), ALp + (size_t)it*8);
        int kr = it*8 + bk;
        const u32* ph_ = BH + (size_t)kr*N + bn + bn4;
        const u32* pl_ = BL + (size_t)kr*N + bn + bn4;
        if (!NGUARD){
            cp16(s2u(&sm->BsH[buf][bk][bn4]), ph_);
            cp16(s2u(&sm->BsL[buf][bk][bn4]), pl_);
        } else {
            int col = bn + bn4;
            int sz = (N - col)*4; sz = sz<0?0:(sz>16?16:sz);
            cp16z(s2u(&sm->BsH[buf][bk][bn4]), ph_, sz);
            cp16z(s2u(&sm->BsL[buf][bk][bn4]), pl_, sz);
        }
    };

    issueTile(0, 0); cp_commit();

    int cur = 0;
    for (int it=0; it<nit; ++it){
        cp_wait0();
        __syncthreads();
        if (it+1 < nit){ issueTile(cur^1, it+1); cp_commit(); }

        u32 aH[4][4], aL[4][4];
        #pragma unroll
        for (int mt=0;mt<4;mt++){
            int m0 = wm + mt*16 + gid;
            aH[mt][0]=sm->AsH[cur][m0*12     + tig  ]; aL[mt][0]=sm->AsL[cur][m0*12     + tig  ];
            aH[mt][1]=sm->AsH[cur][(m0+8)*12 + tig  ]; aL[mt][1]=sm->AsL[cur][(m0+8)*12 + tig  ];
            aH[mt][2]=sm->AsH[cur][m0*12     + tig+4]; aL[mt][2]=sm->AsL[cur][m0*12     + tig+4];
            aH[mt][3]=sm->AsH[cur][(m0+8)*12 + tig+4]; aL[mt][3]=sm->AsL[cur][(m0+8)*12 + tig+4];
        }
        u32 bH[4][2], bL[4][2];
        #pragma unroll
        for (int nt=0;nt<4;nt++){
            int n0 = wn + nt*8 + gid;
            bH[nt][0]=sm->BsH[cur][tig  ][n0]; bL[nt][0]=sm->BsL[cur][tig  ][n0];
            bH[nt][1]=sm->BsH[cur][tig+4][n0]; bL[nt][1]=sm->BsL[cur][tig+4][n0];
        }
        #pragma unroll
        for (int mt=0;mt<4;mt++){
            #pragma unroll
            for (int nt=0;nt<4;nt++){
                mma_bf16(c[mt][nt], aH[mt], bH[nt]);
                mma_bf16(c[mt][nt], aH[mt], bL[nt]);
                mma_bf16(c[mt][nt], aL[mt], bH[nt]);
            }
        }
        cur ^= 1;
    }

    #pragma unroll
    for (int mt=0;mt<4;mt++){
        int ra = bm + wm + mt*16 + gid;
        int rb = ra + 8;
        #pragma unroll
        for (int nt=0;nt<4;nt++){
            int col = bn + wn + nt*8 + tig*2;
            if (OSPLIT){
                float v0 = c[mt][nt][0], v1 = c[mt][nt][1];
                float v2 = c[mt][nt][2], v3 = c[mt][nt][3];
                if (BIAS){ float b0=bias[col], b1=bias[col+1]; v0+=b0; v1+=b1; v2+=b0; v3+=b1; }
                if (GELU){ v0=gelu_f(v0); v1=gelu_f(v1); v2=gelu_f(v2); v3=gelu_f(v3); }
                u32 hi, lo;
                packpair(v0, v1, hi, lo);
                OH[(size_t)ra*lda2o + (col>>1)] = hi; OL[(size_t)ra*lda2o + (col>>1)] = lo;
                packpair(v2, v3, hi, lo);
                OH[(size_t)rb*lda2o + (col>>1)] = hi; OL[(size_t)rb*lda2o + (col>>1)] = lo;
            } else {
                #pragma unroll
                for (int q=0;q<4;q++){
                    int r = (q<2)? ra : rb;
                    int cc = col + (q&1);
                    if (NGUARD && cc >= N) continue;
                    float v = c[mt][nt][q];
                    if (BIAS) v += bias[cc];
                    if (GELU) v = gelu_f(v);
                    size_t idx = (size_t)r*N + cc;
                    if (ACC) v += C[idx];
                    C[idx] = v;
                }
            }
        }
    }
}

template<bool ACC, bool GELU, bool BIAS, bool NGUARD, bool OSPLIT>
__global__ __launch_bounds__(256)
void bgemm_kernel(const u32* __restrict__ AH, const u32* __restrict__ AL, int lda2,
                  const u32* __restrict__ BH, const u32* __restrict__ BL,
                  const float* __restrict__ bias, float* __restrict__ C,
                  u32* __restrict__ OH, u32* __restrict__ OL, int lda2o,
                  int N, int K2)
{
    __shared__ GemmS sm;
    gemm_tile<ACC,GELU,BIAS,NGUARD,OSPLIT>(&sm, blockIdx.y*128, blockIdx.x*128,
        AH, AL, lda2, BH, BL, bias, C, OH, OL, lda2o, N, K2);
}

// ---- attention ----
__global__ void attn_s_kernel(){
    int bh = blockIdx.y;
    int b = bh >> 3, h = bh & 7;
    int qt = blockIdx.x >> 3, kt = blockIdx.x & 7;
    __shared__ float Qs[32][65];
    __shared__ float Ks[32][65];
    int tid = threadIdx.x;
    {
        int r = tid >> 3, cc = (tid & 7)*8;
        const float* qsrc = g_q + ((size_t)(b*TT + qt*32 + r))*EE + h*DHH + cc;
        const float* ksrc = g_k + ((size_t)(b*TT + kt*32 + r))*EE + h*DHH + cc;
        float4 q0 = *(const float4*)qsrc, q1 = *(const float4*)(qsrc+4);
        float4 k0 = *(const float4*)ksrc, k1 = *(const float4*)(ksrc+4);
        Qs[r][cc+0]=q0.x; Qs[r][cc+1]=q0.y; Qs[r][cc+2]=q0.z; Qs[r][cc+3]=q0.w;
        Qs[r][cc+4]=q1.x; Qs[r][cc+5]=q1.y; Qs[r][cc+6]=q1.z; Qs[r][cc+7]=q1.w;
        Ks[r][cc+0]=k0.x; Ks[r][cc+1]=k0.y; Ks[r][cc+2]=k0.z; Ks[r][cc+3]=k0.w;
        Ks[r][cc+4]=k1.x; Ks[r][cc+5]=k1.y; Ks[r][cc+6]=k1.z; Ks[r][cc+7]=k1.w;
    }
    __syncthreads();
    int r = tid & 31, gq = tid >> 5;
    float a0=0,a1=0,a2=0,a3=0;
    #pragma unroll
    for (int kk=0;kk<64;kk++){
        float qv = Qs[r][kk];
        a0 += qv*Ks[gq*4+0][kk];
        a1 += qv*Ks[gq*4+1][kk];
        a2 += qv*Ks[gq*4+2][kk];
        a3 += qv*Ks[gq*4+3][kk];
    }
    int qrow = qt*32 + r;
    int kc = kt*32 + gq*4;
    float* srow = g_s + ((size_t)bh*TT + qrow)*TT + kc;
    srow[0] = (kc+0<=qrow)? a0*0.125f : -1e30f;
    srow[1] = (kc+1<=qrow)? a1*0.125f : -1e30f;
    srow[2] = (kc+2<=qrow)? a2*0.125f : -1e30f;
    srow[3] = (kc+3<=qrow)? a3*0.125f : -1e30f;
}

__global__ void softmax_kernel(){
    int row = blockIdx.x, tid = threadIdx.x;
    __shared__ float red[256];
    float* sp = g_s + (size_t)row*TT;
    float v = sp[tid];
    red[tid]=v; __syncthreads();
    for (int s=128;s>0;s>>=1){ if (tid<s) red[tid]=fmaxf(red[tid],red[tid+s]); __syncthreads(); }
    float m = red[0]; __syncthreads();
    float e = expf(v-m);
    red[tid]=e; __syncthreads();
    for (int s=128;s>0;s>>=1){ if (tid<s) red[tid]+=red[tid+s]; __syncthreads(); }
    sp[tid] = e / red[0];
}

__global__ void attn_o_kernel(){
    int bh = blockIdx.y;
    int b = bh >> 3, h = bh & 7;
    int qt = blockIdx.x;
    __shared__ float As[32][65];
    __shared__ float Vs[64][64];
    int tid = threadIdx.x;
    int d = tid & 63, qg = tid >> 6;
    float acc[8];
    #pragma unroll
    for (int i=0;i<8;i++) acc[i]=0.f;
    for (int k0=0;k0<TT;k0+=64){
        {
            int r = tid >> 3, cc = (tid & 7)*8;
            const float* src = g_s + ((size_t)bh*TT + qt*32 + r)*TT + k0 + cc;
            float4 a0=*(const float4*)src, a1=*(const float4*)(src+4);
            As[r][cc+0]=a0.x; As[r][cc+1]=a0.y; As[r][cc+2]=a0.z; As[r][cc+3]=a0.w;
            As[r][cc+4]=a1.x; As[r][cc+5]=a1.y; As[r][cc+6]=a1.z; As[r][cc+7]=a1.w;
        }
        #pragma unroll
        for (int i=0;i<4;i++){
            int fl = (tid + 256*i)*4;
            int r = fl >> 6, cc = fl & 63;
            float4 vv = *(const float4*)(g_v + ((size_t)(b*TT + k0 + r))*EE + h*DHH + cc);
            *(float4*)&Vs[r][cc] = vv;
        }
        __syncthreads();
        #pragma unroll
        for (int kk=0;kk<64;kk++){
            float vv = Vs[kk][d];
            #pragma unroll
            for (int i=0;i<8;i++) acc[i] += As[qg*8+i][kk]*vv;
        }
        __syncthreads();
    }
    #pragma unroll
    for (int i=0;i<8;i++){
        int qr = qt*32 + qg*8 + i;
        float other = __shfl_xor_sync(0xffffffffu, acc[i], 1);
        if ((d & 1) == 0){
            u32 hi, lo; packpair(acc[i], other, hi, lo);
            int pc = (h*DHH + d) >> 1;
            size_t row = (size_t)(b*TT + qr);
            g_bh[row*256 + pc] = hi;
            g_bl[row*256 + pc] = lo;
        }
    }
}

// ---- init ----
__global__ void meminit_kernel(const float* __restrict__ mi){
    int idx = blockIdx.x*256 + threadIdx.x;
    g_mem[idx] = mi[idx & (NN*DD - 1)];
}
__global__ void norminit_kernel(){
    int gw = blockIdx.x*8 + (threadIdx.x>>5);
    int lane = threadIdx.x & 31;
    const float2* mrow = (const float2*)(g_mem + (size_t)gw*HDD);
    float2 v = mrow[lane];
    float ss = v.x*v.x + v.y*v.y;
    #pragma unroll
    for (int o=16;o>0;o>>=1) ss += __shfl_xor_sync(0xffffffffu, ss, o);
    if (lane==0) g_norminv[gw] = rsqrtf(ss + 1e-8f);
}
__global__ void scaninit_kernel(){
    int i = blockIdx.x*256 + threadIdx.x;
    g_rvbuf[0][i] = 0.f;
    if (i < BB) g_bar[i] = 0u;
    if (i == BB) g_hdone = 0u;
}

// ---- scan body (256 threads, block-private) ----
__device__ void scan_body(ScanS* sp_, const float* __restrict__ Wr,
                          const float* __restrict__ pbr, const float* __restrict__ pbw)
{
    int bh = blockIdx.x;
    int b = bh >> 2, h = bh & 3;
    int tid = threadIdx.x, warp = tid>>5, lane = tid&31;
    ScanS& S = *sp_;

    float beta_r = softplus_clip(*pbr);
    float beta_w = softplus_clip(*pbw);

    for (int t=0; t<TT; ++t){
        S.rv[tid] = __ldcg(&g_rvbuf[t&1][b*DD + tid]);
        if (tid==0){ S.cnt[0]=0; S.cnt[1]=0; }
        __syncthreads();
        if (h == 0 && tid < 128){
            u32 hi, lo; packpair(S.rv[2*tid], S.rv[2*tid+1], hi, lo);
            size_t row = (size_t)(b*TT + t);
            g_ah[row*384 + 256 + tid] = hi;
            g_al[row*384 + 256 + tid] = lo;
        }

        {
            int cq = tid & 63, dg = tid >> 6;
            int seg = cq >> 4, cl4 = (cq & 15)*4;
            int col = seg*DD + h*HDD + cl4;
            const float* wp = Wr + (size_t)(dg*64)*IFF + col;
            float ax=0.f, ay=0.f, az=0.f, aw=0.f;
            #pragma unroll 8
            for (int d=0; d<64; ++d){
                float r = S.rv[dg*64 + d];
                float4 w = *reinterpret_cast<const float4*>(wp + (size_t)d*IFF);
                ax += r*w.x; ay += r*w.y; az += r*w.z; aw += r*w.w;
            }
            int p = seg*64 + cl4;
            S.pmat[dg][p+0]=ax; S.pmat[dg][p+1]=ay; S.pmat[dg][p+2]=az; S.pmat[dg][p+3]=aw;
        }
        if (tid < 32){
            int col = 4*DD + h;
            float acc = 0.f;
            for (int d=tid; d<DD; d+=32) acc += S.rv[d]*Wr[(size_t)d*IFF + col];
            #pragma unroll
            for (int o=16;o>0;o>>=1) acc += __shfl_xor_sync(0xffffffffu, acc, o);
            if (tid==0) S.gr = acc + g_iface[(size_t)(b*TT + t)*IFF + col];
        }
        __syncthreads();
        {
            int grp = tid >> 6, l = tid & 63;
            int col = grp*DD + h*HDD + l;
            S.ifc[tid] = g_iface[(size_t)(b*TT + t)*IFF + col]
                       + S.pmat[0][tid] + S.pmat[1][tid] + S.pmat[2][tid] + S.pmat[3][tid];
        }
        __syncthreads();

        if (tid < 64){
            int w = tid >> 5, l = tid & 31;
            float v0 = S.ifc[w*64 + l], v1 = S.ifc[w*64 + l + 32];
            float ss = v0*v0 + v1*v1;
            #pragma unroll
            for (int o=16;o>0;o>>=1) ss += __shfl_xor_sync(0xffffffffu, ss, o);
            float rn = rsqrtf(ss + 1e-8f);
            float* dst = w ? S.knw : S.knr;
            dst[l] = v0*rn; dst[l+32] = v1*rn;
        }
        __syncthreads();

        for (int j=0;j<8;j++){
            int n = j*256 + tid;
            const float4* mrow = (const float4*)(g_mem + (((size_t)b*NN + n)*HMM + h)*HDD);
            float dr=0.f, dw=0.f;
            #pragma unroll
            for (int c2=0;c2<16;c2++){
                float4 m  = mrow[c2];
                float4 kr = *(const float4*)&S.knr[c2*4];
                float4 kw = *(const float4*)&S.knw[c2*4];
                dr += m.x*kr.x + m.y*kr.y + m.z*kr.z + m.w*kr.w;
                dw += m.x*kw.x + m.y*kw.y + m.z*kw.z + m.w*kw.w;
            }
            float ninv = g_norminv[((size_t)b*NN + n)*HMM + h];
            S.simr[n] = dr*ninv;
            S.simw[n] = dw*ninv;
        }
        __syncthreads();

        {
            int ph = warp >> 2, wi = warp & 3;
            const float* sim = ph ? S.simw : S.simr;
            float lv[16];
            #pragma unroll
            for (int j=0;j<16;j++) lv[j] = sim[wi*512 + j*32 + lane];
            #pragma unroll
            for (int it=0; it<TOPKK; ++it){
                float m=-3.4e38f; int mi=0;
                #pragma unroll
                for (int j=0;j<16;j++) if (lv[j]>m){ m=lv[j]; mi=j; }
                float bm=m; int bl=lane;
                #pragma unroll
                for (int o=16;o>0;o>>=1){
                    float om=__shfl_xor_sync(0xffffffffu,bm,o);
                    int   ol=__shfl_xor_sync(0xffffffffu,bl,o);
                    if (om>bm || (om==bm && ol<bl)){ bm=om; bl=ol; }
                }
                if (lane==bl) lv[mi] = -3.4e38f;
                if (lane==0) S.candv[ph][wi*8+it] = bm;
            }
        }
        __syncthreads();
        if ((warp&3)==0){
            int ph = warp>>2;
            float v = S.candv[ph][lane];
            float kth_=0.f, smax_=0.f;
            #pragma unroll
            for (int it=0; it<TOPKK; ++it){
                float bm=v; int bl=lane;
                #pragma unroll
                for (int o=16;o>0;o>>=1){
                    float om=__shfl_xor_sync(0xffffffffu,bm,o);
                    int   ol=__shfl_xor_sync(0xffffffffu,bl,o);
                    if (om>bm || (om==bm && ol<bl)){ bm=om; bl=ol; }
                }
                if (it==0) smax_=bm;
                if (it==TOPKK-1) kth_=bm;
                if (lane==bl) v = -3.4e38f;
            }
            if (lane==0){ S.kth[ph]=kth_; S.smax[ph]=smax_; }
        }
        __syncthreads();

        {
            int ph = tid >> 7, lt = tid & 127;
            const float* sim = ph ? S.simw : S.simr;
            float kth = S.kth[ph], smax = S.smax[ph];
            float beta = ph ? beta_w : beta_r;
            #pragma unroll
            for (int j=0;j<16;j++){
                int i = j*128 + lt;
                float v = sim[i];
                if (v >= kth){
                    int p = atomicAdd(&S.cnt[ph], 1);
                    if (p < MAXSEL){ S.selidx[ph][p]=i; S.selw[ph][p]=expf(beta*(v-smax)); }
                }
            }
        }
        __syncthreads();
        if (tid < 2){
            int cnt = min(S.cnt[tid], MAXSEL);
            float ds=0.f;
            for (int j=0;j<cnt;j++) ds += S.selw[tid][j];
            S.sinv[tid] = 1.0f/ds;
        }
        __syncthreads();

        {
            int cnt = min(S.cnt[0], MAXSEL);
            if (tid < HDD){
                float acc=0.f;
                float invd = S.sinv[0];
                for (int j=0;j<cnt;j++)
                    acc += S.selw[0][j]*invd * g_mem[(((size_t)b*NN + S.selidx[0][j])*HMM + h)*HDD + tid];
                __stcg(&g_rvbuf[(t+1)&1][b*DD + h*HDD + tid], acc);
            }
        }
        __syncthreads();
        if (tid==0) red_release(&g_bar[b], 1u);

        {
            int cnt = min(S.cnt[1], MAXSEL);
            float gg = sigmoid_f(S.gr);
            int d = tid & 63;
            float ee = sigmoid_f(S.ifc[192 + d]);
            float gv = gg * S.ifc[128 + d];
            float invd = S.sinv[1];
            for (int j = tid>>6; j<cnt; j+=4){
                float w = S.selw[1][j]*invd;
                size_t mi = (((size_t)b*NN + S.selidx[1][j])*HMM + h)*HDD + d;
                g_mem[mi] = g_mem[mi]*(1.0f - w*ee) + w*gv;
            }
        }
        __syncthreads();
        {
            int cnt = min(S.cnt[1], MAXSEL);
            for (int j = warp; j < cnt; j += 8){
                int n = S.selidx[1][j];
                const float2* mrow = (const float2*)(g_mem + (((size_t)b*NN + n)*HMM + h)*HDD);
                float2 v = mrow[lane];
                float ss = v.x*v.x + v.y*v.y;
                #pragma unroll
                for (int o=16;o>0;o>>=1) ss += __shfl_xor_sync(0xffffffffu, ss, o);
                if (lane==0) g_norminv[((size_t)b*NN + n)*HMM + h] = rsqrtf(ss + 1e-8f);
            }
        }
        __syncthreads();

        if (tid==0){
            while (ld_acquire(&g_bar[b]) < (u32)HMM*(u32)(t+1)) { }
        }
        __syncthreads();
    }
}

// ---- mega kernel ----
// blocks [0,32):          persistent scan
// blocks [32, 4032):      vocab h-GEMM tiles (K2=256), release g_hdone
// blocks [4032, 8032):    vocab rv-GEMM tiles (K2=128, ACC), wait h-done + scan progress
__global__ __launch_bounds__(256)
void mega_kernel(const float* __restrict__ Wr,
                 const float* __restrict__ pbr,
                 const float* __restrict__ pbw,
                 const float* __restrict__ b_lg,
                 float* __restrict__ out)
{
    __shared__ __align__(16) char smraw[sizeof(GemmS)];
    if (blockIdx.x < 32){
        scan_body((ScanS*)smraw, Wr, pbr, pbw);
    } else if (blockIdx.x < 4032){
        int tile = blockIdx.x - 32;
        int bn = (tile % 250)*128;
        int bm = (tile / 250)*128;
        gemm_tile<false,false,true,false,false>((GemmS*)smraw, bm, bn,
            g_ah, g_al, 384, g_wh + OFF_WLG, g_wl + OFF_WLG,
            b_lg, out, nullptr, nullptr, 0, VV, 256);
        __syncthreads();
        if (threadIdx.x == 0) red_release(&g_hdone, 1u);
    } else {
        int idx = blockIdx.x - 4032;          // 0..3999
        // order: first the 8 even mr (t in [0,128)), then odd mr (t in [128,256))
        int mr = (idx < 2000) ? 2*(idx/250) : 2*((idx-2000)/250) + 1;
        int bn = (idx % 250)*128;
        int bm = mr*128;
        int b = mr >> 1;
        u32 need_bar = (u32)HMM * (u32)(((mr & 1)*128 + 127) + 1);
        if (threadIdx.x == 0){
            while (ld_acquire(&g_hdone) < 4000u) __nanosleep(256);
            while (ld_acquire(&g_bar[b]) < need_bar) __nanosleep(256);
        }
        __syncthreads();
        gemm_tile<true,false,false,false,false>((GemmS*)smraw, bm, bn,
            g_ah + 256, g_al + 256, 384,
            g_wh + OFF_WLG + (size_t)256*VV, g_wl + OFF_WLG + (size_t)256*VV,
            nullptr, out, nullptr, nullptr, 0, VV, 128);
    }
}

extern "C" void kernel_launch(void* const* d_in, const int* in_sizes, int n_in,
                              void* d_out, int out_size)
{
    const int*   ids      = (const int*)  d_in[0];
    const float* emb      = (const float*)d_in[1];
    const float* pos      = (const float*)d_in[2];
    const float* ln1_g    = (const float*)d_in[3];
    const float* ln1_b    = (const float*)d_in[4];
    const float* ln2_g    = (const float*)d_in[5];
    const float* ln2_b    = (const float*)d_in[6];
    const float* Wq       = (const float*)d_in[7];
    const float* Wk       = (const float*)d_in[8];
    const float* Wv       = (const float*)d_in[9];
    const float* Wo       = (const float*)d_in[10];
    const float* W1       = (const float*)d_in[11];
    const float* b1       = (const float*)d_in[12];
    const float* W2       = (const float*)d_in[13];
    const float* b2       = (const float*)d_in[14];
    const float* lnf_g    = (const float*)d_in[15];
    const float* lnf_b    = (const float*)d_in[16];
    const float* W_if_h   = (const float*)d_in[17];
    const float* W_if_r   = (const float*)d_in[18];
    const float* b_if     = (const float*)d_in[19];
    const float* W_lg_h   = (const float*)d_in[20];
    const float* W_lg_r   = (const float*)d_in[21];
    const float* b_lg     = (const float*)d_in[22];
    const float* beta_read  = (const float*)d_in[23];
    const float* beta_write = (const float*)d_in[24];
    const float* mem_init = (const float*)d_in[25];
    float* out = (float*)d_out;

    float *px,*pq,*pk,*pv,*pif;
    u32 *pwh,*pwl,*pah,*pal,*pbh,*pbl;
    cudaGetSymbolAddress((void**)&px,  g_x);
    cudaGetSymbolAddress((void**)&pq,  g_q);
    cudaGetSymbolAddress((void**)&pk,  g_k);
    cudaGetSymbolAddress((void**)&pv,  g_v);
    cudaGetSymbolAddress((void**)&pif, g_iface);
    cudaGetSymbolAddress((void**)&pwh, g_wh);
    cudaGetSymbolAddress((void**)&pwl, g_wl);
    cudaGetSymbolAddress((void**)&pah, g_ah);
    cudaGetSymbolAddress((void**)&pal, g_al);
    cudaGetSymbolAddress((void**)&pbh, g_bh);
    cudaGetSymbolAddress((void**)&pbl, g_bl);

    const int M = BB*TT;

    embed_kernel<<<M,256>>>(ids, emb, pos);
    wsplit_kernel<<<dim3(2,512),256>>>(Wq, pwh+OFF_QKVO_W(0), pwl+OFF_QKVO_W(0), EE);
    wsplit_kernel<<<dim3(2,512),256>>>(Wk, pwh+OFF_QKVO_W(1), pwl+OFF_QKVO_W(1), EE);
    wsplit_kernel<<<dim3(2,512),256>>>(Wv, pwh+OFF_QKVO_W(2), pwl+OFF_QKVO_W(2), EE);

    for (int l=0; l<LL; ++l){
        ln_split_kernel<<<M,256>>>(px, ln1_g + l*EE, ln1_b + l*EE, pbh, pbl, 256);
        bgemm_kernel<false,false,false,false,false><<<dim3(4,16),256>>>(pbh, pbl, 256,
            pwh+OFF_QKVO_W(0)+l*131072, pwl+OFF_QKVO_W(0)+l*131072,
            nullptr, pq, nullptr, nullptr, 0, EE, 256);
        bgemm_kernel<false,false,false,false,false><<<dim3(4,16),256>>>(pbh, pbl, 256,
            pwh+OFF_QKVO_W(1)+l*131072, pwl+OFF_QKVO_W(1)+l*131072,
            nullptr, pk, nullptr, nullptr, 0, EE, 256);
        bgemm_kernel<false,false,false,false,false><<<dim3(4,16),256>>>(pbh, pbl, 256,
            pwh+OFF_QKVO_W(2)+l*131072, pwl+OFF_QKVO_W(2)+l*131072,
            nullptr, pv, nullptr, nullptr, 0, EE, 256);
        attn_s_kernel<<<dim3(64, BB*HAA),256>>>();
        softmax_kernel<<<BB*HAA*TT,256>>>();
        attn_o_kernel<<<dim3(8, BB*HAA),256>>>();
        if (l==0)
            wsplit_kernel<<<dim3(2,512),256>>>(Wo, pwh+OFF_QKVO_W(3), pwl+OFF_QKVO_W(3), EE);
        bgemm_kernel<true,false,false,false,false><<<dim3(4,16),256>>>(pbh, pbl, 256,
            pwh+OFF_QKVO_W(3)+l*131072, pwl+OFF_QKVO_W(3)+l*131072,
            nullptr, px, nullptr, nullptr, 0, EE, 256);
        ln_split_kernel<<<M,256>>>(px, ln2_g + l*EE, ln2_b + l*EE, pbh, pbl, 256);
        if (l==0){
            wsplit_kernel<<<dim3(8,512),256>>>(W1, pwh+OFF_W1, pwl+OFF_W1, FF);
            wsplit_kernel<<<dim3(2,2048),256>>>(W2, pwh+OFF_W2, pwl+OFF_W2, EE);
        }
        bgemm_kernel<false,true,true,false,true><<<dim3(16,16),256>>>(pbh, pbl, 256,
            pwh+OFF_W1+l*524288, pwl+OFF_W1+l*524288,
            b1 + l*FF, nullptr, pah, pal, 1024, FF, 256);
        bgemm_kernel<true,false,true,false,false><<<dim3(4,16),256>>>(pah, pal, 1024,
            pwh+OFF_W2+l*524288, pwl+OFF_W2+l*524288,
            b2 + l*EE, px, nullptr, nullptr, 0, EE, 1024);
    }

    // final LN -> vocab-A planes cols [0,256)
    ln_split_kernel<<<M,256>>>(px, lnf_g, lnf_b, pah, pal, 384);

    // iface = h @ W_if_h + b_if
    wsplit_kernel<<<dim3(5,256),256>>>(W_if_h, pwh+OFF_WIFH, pwl+OFF_WIFH, IFF);
    bgemm_kernel<false,false,true,true,false><<<dim3(9,16),256>>>(pah, pal, 384,
        pwh+OFF_WIFH, pwl+OFF_WIFH, b_if, pif, nullptr, nullptr, 0, IFF, 256);

    // vocab weight splits (must precede mega)
    wsplit_kernel<<<dim3(125,256),256>>>(W_lg_h, pwh+OFF_WLG, pwl+OFF_WLG, VV);
    wsplit_kernel<<<dim3(125,128),256>>>(W_lg_r, pwh+OFF_WLG+(size_t)256*VV,
                                         pwl+OFF_WLG+(size_t)256*VV, VV);

    meminit_kernel<<<16384,256>>>(mem_init);
    norminit_kernel<<<BB*NN*HMM/8,256>>>();
    scaninit_kernel<<<8,256>>>();

    // mega: scan + vocab h-GEMM + vocab rv-GEMM all overlapped
    mega_kernel<<<32 + 4000 + 4000, 256>>>(W_if_r, beta_read, beta_write, b_lg, out);
}